// round 7
// baseline (speedup 1.0000x reference)
#include <cuda_runtime.h>
#include <math.h>

#define B_   4
#define T_   1024
#define D_   512
#define H_   2048
#define L_   6
#define WIN  64
#define MT   (B_*T_)          // 4096 rows
#define NBTD (B_*T_*D_)       // 2,097,152

// ---------------- scratch (static __device__, alloc-free) ----------------
__device__ float g_E[NBTD];        // emb = h + pos (residual source)
__device__ float g_Q[NBTD];        // q, later y
__device__ float g_K[NBTD];        // k, later ek, later A (attn pre-LN)
__device__ float g_V[NBTD];        // v, later ek*v, later attn_out (post-LN)
__device__ float g_F1[MT*H_];      // FFN hidden
__device__ float g_ew[T_*WIN];     // banded exp weights per layer
__device__ float g_kpart[B_*8*D_]; // partial k-max
__device__ float g_kmax[B_*D_];    // k-max over T per (b,d)

// ---------------- embedding: h = tok_emb[x]*s + pos*s ----------------
__global__ void k_embed(const int* __restrict__ x, const float* __restrict__ tok,
                        const float* __restrict__ pos, float* __restrict__ h) {
    int i = blockIdx.x * blockDim.x + threadIdx.x;
    if (i >= NBTD) return;
    int d  = i % D_;
    int bt = i / D_;
    int t  = bt % T_;
    float s = rsqrtf((float)D_);
    h[i] = tok[(long)x[bt]*D_ + d] * s + pos[t*D_ + d] * s;
}

// ---------------- emb = h + pos*s ----------------
__global__ void k_addpos(const float* __restrict__ h, const float* __restrict__ pos,
                         float* __restrict__ e) {
    int i = blockIdx.x * blockDim.x + threadIdx.x;
    if (i >= NBTD) return;
    int td = i % (T_*D_);
    float s = rsqrtf((float)D_);
    e[i] = h[i] + pos[td] * s;
}

// ---------------- SGEMM: C[M,N] = A[M,K] @ B[K,N] + bias (opt ReLU) ----------------
// BM=BN=128, BK=8, 256 threads, 8x8 per thread, double-buffered smem.
template<int RELU>
__global__ __launch_bounds__(256, 2)
void k_gemm(const float* __restrict__ A, const float* __restrict__ Bm,
            const float* __restrict__ bias, float* __restrict__ C,
            int M, int N, int K) {
    __shared__ float As[2][8][128];
    __shared__ float Bs[2][8][128];

    int tid = threadIdx.x;
    int bm = blockIdx.y * 128, bn = blockIdx.x * 128;
    int arow = tid >> 1,  acol = (tid & 1) * 4;   // A tile: 128x8
    int brow = tid >> 5,  bcol = (tid & 31) * 4;  // B tile: 8x128
    int ty = tid >> 4,    tx = tid & 15;

    const float* Ap = A  + (long)(bm + arow) * K + acol;
    const float* Bp = Bm + (long)brow * N + bn + bcol;

    float4 ra = *(const float4*)(Ap);
    float4 rb = *(const float4*)(Bp);
    As[0][acol+0][arow] = ra.x; As[0][acol+1][arow] = ra.y;
    As[0][acol+2][arow] = ra.z; As[0][acol+3][arow] = ra.w;
    *(float4*)&Bs[0][brow][bcol] = rb;
    __syncthreads();

    float acc[8][8] = {};
    int nt = K >> 3;
    for (int kt = 0; kt < nt; kt++) {
        int cur = kt & 1;
        if (kt + 1 < nt) {
            ra = *(const float4*)(Ap + (kt+1)*8);
            rb = *(const float4*)(Bp + (long)(kt+1)*8*N);
        }
#pragma unroll
        for (int kk = 0; kk < 8; kk++) {
            float av[8], bv[8];
#pragma unroll
            for (int i = 0; i < 8; i++) av[i] = As[cur][kk][ty*8 + i];
#pragma unroll
            for (int j = 0; j < 8; j++) bv[j] = Bs[cur][kk][tx*8 + j];
#pragma unroll
            for (int i = 0; i < 8; i++)
#pragma unroll
                for (int j = 0; j < 8; j++)
                    acc[i][j] = fmaf(av[i], bv[j], acc[i][j]);
        }
        if (kt + 1 < nt) {
            int nb = cur ^ 1;
            As[nb][acol+0][arow] = ra.x; As[nb][acol+1][arow] = ra.y;
            As[nb][acol+2][arow] = ra.z; As[nb][acol+3][arow] = ra.w;
            *(float4*)&Bs[nb][brow][bcol] = rb;
        }
        __syncthreads();
    }

#pragma unroll
    for (int i = 0; i < 8; i++) {
        int m = bm + ty*8 + i;
#pragma unroll
        for (int j = 0; j < 8; j++) {
            int n = bn + tx*8 + j;
            float v = acc[i][j] + bias[n];
            if (RELU) v = fmaxf(v, 0.f);
            C[(long)m*N + n] = v;
        }
    }
}

// ---------------- banded exp(w_bias) with row-max stabilization ----------------
// ew[t][j] = exp(w_bias[t, t-j] - rowmax)  for j in [0, min(t,63)], else 0
__global__ void k_ew(const float* __restrict__ wb, float* __restrict__ ew) {
    int t = blockIdx.x;
    int j = threadIdx.x;              // 64 threads
    bool valid = (j <= t);
    float w = valid ? wb[(long)t*T_ + (t - j)] : -1e30f;
    __shared__ float sm[64];
    sm[j] = w; __syncthreads();
    for (int off = 32; off > 0; off >>= 1) {
        if (j < off) sm[j] = fmaxf(sm[j], sm[j+off]);
        __syncthreads();
    }
    float m = sm[0];
    ew[t*WIN + j] = valid ? expf(w - m) : 0.f;
}

// ---------------- k-max over T per (b,d): two-phase ----------------
__global__ void k_kmax_part(const float* __restrict__ K, float* __restrict__ part) {
    int b = blockIdx.y, z = blockIdx.x, d = threadIdx.x;  // 512 threads
    float m = -INFINITY;
    int t0 = z * (T_/8);
#pragma unroll 4
    for (int t = t0; t < t0 + T_/8; t++)
        m = fmaxf(m, K[((long)b*T_ + t)*D_ + d]);
    part[(b*8 + z)*D_ + d] = m;
}
__global__ void k_kmax_red(const float* __restrict__ part, float* __restrict__ kmax) {
    int b = blockIdx.x, d = threadIdx.x;
    float m = -INFINITY;
#pragma unroll
    for (int z = 0; z < 8; z++) m = fmaxf(m, part[(b*8 + z)*D_ + d]);
    kmax[b*D_ + d] = m;
}

// ---------------- ek = exp(k - kmax); ekv = ek * v (in place) ----------------
__global__ void k_ekv(float* __restrict__ K, float* __restrict__ V,
                      const float* __restrict__ kmax) {
    int i = blockIdx.x * blockDim.x + threadIdx.x;
    if (i >= NBTD) return;
    int d = i % D_;
    int b = i / (T_*D_);
    float ek = expf(K[i] - kmax[b*D_ + d]);
    K[i] = ek;
    V[i] = ek * V[i];
}

// ---------------- banded AFT: y = sigmoid(q) * num/(den+1e-9) ----------------
__global__ void k_band(const float* __restrict__ Q, const float* __restrict__ EK,
                       const float* __restrict__ EKV, const float* __restrict__ ew,
                       float* __restrict__ Y) {
    int t = blockIdx.x, b = blockIdx.y;
    int tid = threadIdx.x;            // 256 threads, 2 d-values each
    __shared__ float sw[WIN];
    if (tid < WIN) sw[tid] = ew[t*WIN + tid];
    __syncthreads();
    int jmax = min(t, WIN - 1);
    long rowt = ((long)b*T_ + t) * D_;
#pragma unroll
    for (int r = 0; r < 2; r++) {
        int d = tid + r*256;
        float num = 0.f, den = 0.f;
        for (int j = 0; j <= jmax; j++) {
            float w = sw[j];
            long rowu = ((long)b*T_ + (t - j)) * D_;
            num = fmaf(w, EKV[rowu + d], num);
            den = fmaf(w, EK [rowu + d], den);
        }
        float q = Q[rowt + d];
        float sig = 1.f / (1.f + expf(-q));
        Y[rowt + d] = sig * num / (den + 1e-9f);
    }
}

// ---------------- out = LayerNorm(X + R) * g + beta ----------------
__global__ void k_resid_ln(const float* __restrict__ X, const float* __restrict__ R,
                           const float* __restrict__ g, const float* __restrict__ bta,
                           float* __restrict__ out) {
    int row = blockIdx.x;
    int tid = threadIdx.x;            // 256 threads, D=512
    long base = (long)row * D_;
    float x0 = X[base + tid]       + R[base + tid];
    float x1 = X[base + tid + 256] + R[base + tid + 256];
    __shared__ float2 red[256];
    red[tid] = make_float2(x0 + x1, x0*x0 + x1*x1);
    __syncthreads();
    for (int off = 128; off > 0; off >>= 1) {
        if (tid < off) {
            red[tid].x += red[tid+off].x;
            red[tid].y += red[tid+off].y;
        }
        __syncthreads();
    }
    float mean = red[0].x * (1.f/D_);
    float var  = red[0].y * (1.f/D_) - mean*mean;
    float rs = rsqrtf(var + 1e-5f);
    out[base + tid]       = (x0 - mean)*rs*g[tid]       + bta[tid];
    out[base + tid + 256] = (x1 - mean)*rs*g[tid + 256] + bta[tid + 256];
}

// ---------------- orchestration ----------------
extern "C" void kernel_launch(void* const* d_in, const int* in_sizes, int n_in,
                              void* d_out, int out_size) {
    const int*   x     = (const int*)  d_in[0];
    const float* tok   = (const float*)d_in[1];
    const float* pos   = (const float*)d_in[2];
    const float* Wq    = (const float*)d_in[3];
    const float* bq    = (const float*)d_in[4];
    const float* Wk    = (const float*)d_in[5];
    const float* bk    = (const float*)d_in[6];
    const float* Wv    = (const float*)d_in[7];
    const float* bv    = (const float*)d_in[8];
    const float* Wo    = (const float*)d_in[9];
    const float* bo    = (const float*)d_in[10];
    const float* wbias = (const float*)d_in[11];
    const float* lng   = (const float*)d_in[12];
    const float* lnb   = (const float*)d_in[13];
    const float* W1    = (const float*)d_in[14];
    const float* b1    = (const float*)d_in[15];
    const float* W2    = (const float*)d_in[16];
    const float* b2    = (const float*)d_in[17];
    float* H = (float*)d_out;   // residual stream lives in d_out

    float *E, *Q, *K, *V, *F1, *EW, *KP, *KM;
    cudaGetSymbolAddress((void**)&E,  g_E);
    cudaGetSymbolAddress((void**)&Q,  g_Q);
    cudaGetSymbolAddress((void**)&K,  g_K);
    cudaGetSymbolAddress((void**)&V,  g_V);
    cudaGetSymbolAddress((void**)&F1, g_F1);
    cudaGetSymbolAddress((void**)&EW, g_ew);
    cudaGetSymbolAddress((void**)&KP, g_kpart);
    cudaGetSymbolAddress((void**)&KM, g_kmax);

    const int EL_BLK = 256;
    const int EL_GRID = (NBTD + EL_BLK - 1) / EL_BLK;
    dim3 g512(D_/128, MT/128);    // (4, 32)
    dim3 gH  (H_/128, MT/128);    // (16, 32)

    k_embed<<<EL_GRID, EL_BLK>>>(x, tok, pos, H);

    for (int i = 0; i < L_; i++) {
        const float* Wqi = Wq + (long)i*D_*D_;  const float* bqi = bq + i*D_;
        const float* Wki = Wk + (long)i*D_*D_;  const float* bki = bk + i*D_;
        const float* Wvi = Wv + (long)i*D_*D_;  const float* bvi = bv + i*D_;
        const float* Woi = Wo + (long)i*D_*D_;  const float* boi = bo + i*D_;
        const float* W1i = W1 + (long)i*D_*H_;  const float* b1i = b1 + i*H_;
        const float* W2i = W2 + (long)i*H_*D_;  const float* b2i = b2 + i*D_;
        const float* wbi = wbias + (long)i*T_*T_;
        const float* gi  = lng + i*D_;
        const float* bi  = lnb + i*D_;

        // emb = h + pos*s
        k_addpos<<<EL_GRID, EL_BLK>>>(H, pos, E);

        // q,k,v projections
        k_gemm<0><<<g512, 256>>>(E, Wqi, bqi, Q, MT, D_, D_);
        k_gemm<0><<<g512, 256>>>(E, Wki, bki, K, MT, D_, D_);
        k_gemm<0><<<g512, 256>>>(E, Wvi, bvi, V, MT, D_, D_);

        // banded position weights
        k_ew<<<T_, WIN>>>(wbi, EW);

        // key max over T, then ek / ek*v in place
        k_kmax_part<<<dim3(8, B_), D_>>>(K, KP);
        k_kmax_red<<<B_, D_>>>(KP, KM);
        k_ekv<<<EL_GRID, EL_BLK>>>(K, V, KM);

        // banded aggregation + gate -> Y (in place over Q)
        k_band<<<dim3(T_, B_), 256>>>(Q, K, V, EW, Q);

        // output projection -> A (reuse K)
        k_gemm<0><<<g512, 256>>>(Q, Woi, boi, K, MT, D_, D_);

        // attn_out = LN(A + emb) -> reuse V
        k_resid_ln<<<MT, 256>>>(K, E, gi, bi, V);

        // FFN
        k_gemm<1><<<gH,   256>>>(V,  W1i, b1i, F1, MT, H_, D_);
        k_gemm<0><<<g512, 256>>>(F1, W2i, b2i, E,  MT, D_, H_);   // F2 -> reuse E

        // h = LN(F2 + attn_out) -> residual stream (d_out)
        k_resid_ln<<<MT, 256>>>(E, V, gi, bi, H);
    }
}

// round 9
// speedup vs baseline: 1.9318x; 1.9318x over previous
#include <cuda_runtime.h>
#include <cuda_bf16.h>
#include <math.h>
#include <stdint.h>

#define B_   4
#define T_   1024
#define D_   512
#define H_   2048
#define L_   6
#define WIN  64
#define MT   (B_*T_)          // 4096 rows
#define NBTD (B_*T_*D_)       // 2,097,152

// per-layer packed weight block: Wq,Wk,Wv,Wo (each 512*512) + W1t (2048*512) + W2t (512*2048)
#define WL   (4*D_*D_ + D_*H_ + H_*D_)
#define OFF_WQ 0
#define OFF_WK (D_*D_)
#define OFF_WV (2*D_*D_)
#define OFF_WO (3*D_*D_)
#define OFF_W1 (4*D_*D_)
#define OFF_W2 (4*D_*D_ + D_*H_)

// ---------------- scratch (static __device__, alloc-free) ----------------
__device__ __align__(16) float g_E[NBTD];
__device__ __align__(16) float g_QKV[3*NBTD];
__device__ __align__(16) float g_A[NBTD];
__device__ __align__(16) float g_AOf[NBTD];
__device__ __align__(16) __nv_bfloat16 g_Eh[NBTD],  g_El[NBTD];
__device__ __align__(16) __nv_bfloat16 g_Yh[NBTD],  g_Yl[NBTD];
__device__ __align__(16) __nv_bfloat16 g_AOh[NBTD], g_AOl[NBTD];
__device__ __align__(16) __nv_bfloat16 g_F1h[MT*H_], g_F1l[MT*H_];
__device__ __align__(16) __nv_bfloat16 g_Wth[L_*WL], g_Wtl[L_*WL];
__device__ __align__(16) float g_bpack[L_*3*D_];
__device__ float g_ew[T_*WIN];
__device__ float g_kpart[B_*8*D_];
__device__ float g_kmax[B_*D_];

// ---------------- helpers ----------------
__device__ __forceinline__ void split2(float x, __nv_bfloat16* h, __nv_bfloat16* l) {
    __nv_bfloat16 hh = __float2bfloat16(x);
    *h = hh;
    *l = __float2bfloat16(x - __bfloat162float(hh));
}
__device__ __forceinline__ uint32_t smem_u32(const void* p) {
    uint32_t a;
    asm("{ .reg .u64 t; cvta.to.shared.u64 t, %1; cvt.u32.u64 %0, t; }" : "=r"(a) : "l"(p));
    return a;
}
__device__ __forceinline__ void cpa16(uint32_t s, const void* g) {
    asm volatile("cp.async.cg.shared.global [%0], [%1], 16;" :: "r"(s), "l"(g));
}
__device__ __forceinline__ void ldmx4(uint32_t* r, uint32_t addr) {
    asm volatile("ldmatrix.sync.aligned.m8n8.x4.shared.b16 {%0,%1,%2,%3}, [%4];"
        : "=r"(r[0]), "=r"(r[1]), "=r"(r[2]), "=r"(r[3]) : "r"(addr));
}
__device__ __forceinline__ void mma16816(float* c, const uint32_t* a, uint32_t b0, uint32_t b1) {
    asm volatile("mma.sync.aligned.m16n8k16.row.col.f32.bf16.bf16.f32 "
        "{%0,%1,%2,%3}, {%4,%5,%6,%7}, {%8,%9}, {%0,%1,%2,%3};"
        : "+f"(c[0]), "+f"(c[1]), "+f"(c[2]), "+f"(c[3])
        : "r"(a[0]), "r"(a[1]), "r"(a[2]), "r"(a[3]), "r"(b0), "r"(b1));
}

// ---------------- HMMA GEMM: C[M,N] = (Ah+Al)(Bh+Bl)^T + bias ----------------
// A: [M,K] bf16 hi/lo; B: [N,K] bf16 hi/lo (K-major). grid (N/128, M/128, NZ).
// SMEM per stage: 4 sub-tiles of 8KB (Ah,Al,Bh,Bl); each laid out as
// 8x8-element atoms: offset = (row/8)*512 + kchunk*128 + (row%8)*16.
#define STAGES 4
#define SSTAGE 32768
#define SA_H 0
#define SA_L 8192
#define SB_H 16384
#define SB_L 24576
#define DSM_BYTES (STAGES*SSTAGE)

template<int RELU, int OUTF, int OUTB>
__global__ void __launch_bounds__(256, 1)
tc_gemm(const __nv_bfloat16* __restrict__ Ah_, const __nv_bfloat16* __restrict__ Al_,
        const __nv_bfloat16* __restrict__ Bh_, const __nv_bfloat16* __restrict__ Bl_,
        const float* __restrict__ bias_, float* Cf_,
        __nv_bfloat16* Ch_, __nv_bfloat16* Cl_,
        int M, int N, int K, long sB, long sBias, long sC) {
    extern __shared__ __align__(1024) char dsm[];
    int t = threadIdx.x;
    int wid = t >> 5, l = t & 31;
    int wy = wid & 3, wx = wid >> 2;       // warp tile: rows wy*32, cols wx*64
    int z = blockIdx.z;
    int bn = blockIdx.x * 128, bm = blockIdx.y * 128;

    const __nv_bfloat16* Ahp = Ah_;
    const __nv_bfloat16* Alp = Al_;
    const __nv_bfloat16* Bhp = Bh_ + (long)z * sB;
    const __nv_bfloat16* Blp = Bl_ + (long)z * sB;
    const float* bias = bias_ + (long)z * sBias;
    float* Cf = Cf_ ? (Cf_ + (long)z * sC) : nullptr;

    uint32_t sbase = smem_u32(dsm);

    // per-thread cp.async mapping: idx=rep*256+t -> row=idx/4, kchunk=idx%4
    int ra = t >> 2, kb = t & 3;
    int rb2 = ra + 64;
    long gA0 = (long)(bm + ra)  * K + kb * 8;
    long gA1 = (long)(bm + rb2) * K + kb * 8;
    long gB0 = (long)(bn + ra)  * K + kb * 8;
    long gB1 = (long)(bn + rb2) * K + kb * 8;
    uint32_t sO0 = (uint32_t)((ra  >> 3) * 512 + kb * 128 + (ra  & 7) * 16);
    uint32_t sO1 = (uint32_t)((rb2 >> 3) * 512 + kb * 128 + (rb2 & 7) * 16);

    auto load_stage = [&](int st, int kc) {
        uint32_t sb = sbase + st * SSTAGE;
        cpa16(sb + SA_H + sO0, Ahp + gA0 + kc);
        cpa16(sb + SA_H + sO1, Ahp + gA1 + kc);
        cpa16(sb + SA_L + sO0, Alp + gA0 + kc);
        cpa16(sb + SA_L + sO1, Alp + gA1 + kc);
        cpa16(sb + SB_H + sO0, Bhp + gB0 + kc);
        cpa16(sb + SB_H + sO1, Bhp + gB1 + kc);
        cpa16(sb + SB_L + sO0, Blp + gB0 + kc);
        cpa16(sb + SB_L + sO1, Blp + gB1 + kc);
    };

    // ldmatrix fragment offsets (within a sub-tile)
    uint32_t lr = (uint32_t)((l & 7) * 16);
    uint32_t offA[2][2], offB[4][2];
#pragma unroll
    for (int mi = 0; mi < 2; mi++)
#pragma unroll
        for (int ks = 0; ks < 2; ks++) {
            int tr = wy*4 + mi*2 + ((l >> 3) & 1);
            int tk = ks*2 + ((l >> 4) & 1);
            offA[mi][ks] = (uint32_t)((tr*4 + tk) * 128) + lr;
        }
#pragma unroll
    for (int j = 0; j < 4; j++)
#pragma unroll
        for (int ks = 0; ks < 2; ks++) {
            int tn = wx*8 + 2*j + ((l >> 4) & 1);
            int tk = ks*2 + ((l >> 3) & 1);
            offB[j][ks] = (uint32_t)((tn*4 + tk) * 128) + lr;
        }

    int nk = K >> 5;
    load_stage(0, 0);   asm volatile("cp.async.commit_group;");
    load_stage(1, 32);  asm volatile("cp.async.commit_group;");
    load_stage(2, 64);  asm volatile("cp.async.commit_group;");
    asm volatile("cp.async.wait_group 2;");
    __syncthreads();

    float acc[2][8][4] = {};

    for (int kt = 0; kt < nk; kt++) {
        if (kt + 3 < nk) load_stage((kt + 3) & 3, (kt + 3) * 32);
        asm volatile("cp.async.commit_group;");

        uint32_t sb = sbase + (kt & 3) * SSTAGE;
#pragma unroll
        for (int ks = 0; ks < 2; ks++) {
            uint32_t ah[2][4], al[2][4], bh[4][4], bl[4][4];
#pragma unroll
            for (int mi = 0; mi < 2; mi++) {
                ldmx4(ah[mi], sb + SA_H + offA[mi][ks]);
                ldmx4(al[mi], sb + SA_L + offA[mi][ks]);
            }
#pragma unroll
            for (int j = 0; j < 4; j++) {
                ldmx4(bh[j], sb + SB_H + offB[j][ks]);
                ldmx4(bl[j], sb + SB_L + offB[j][ks]);
            }
#pragma unroll
            for (int mi = 0; mi < 2; mi++)
#pragma unroll
                for (int j = 0; j < 4; j++) {
                    mma16816(acc[mi][2*j],   ah[mi], bh[j][0], bh[j][1]);
                    mma16816(acc[mi][2*j+1], ah[mi], bh[j][2], bh[j][3]);
                    mma16816(acc[mi][2*j],   ah[mi], bl[j][0], bl[j][1]);
                    mma16816(acc[mi][2*j+1], ah[mi], bl[j][2], bl[j][3]);
                    mma16816(acc[mi][2*j],   al[mi], bh[j][0], bh[j][1]);
                    mma16816(acc[mi][2*j+1], al[mi], bh[j][2], bh[j][3]);
                }
        }
        asm volatile("cp.async.wait_group 2;");
        __syncthreads();
    }

    // epilogue: c-fragment -> gmem, bias/ReLU/split fused
    int gid = l >> 2, tg = l & 3;
#pragma unroll
    for (int mi = 0; mi < 2; mi++) {
        int row0 = bm + wy*32 + mi*16 + gid;
#pragma unroll
        for (int nt = 0; nt < 8; nt++) {
            int col = bn + wx*64 + nt*8 + tg*2;
            float b0v = bias[col], b1v = bias[col + 1];
            float v00 = acc[mi][nt][0] + b0v, v01 = acc[mi][nt][1] + b1v;
            float v10 = acc[mi][nt][2] + b0v, v11 = acc[mi][nt][3] + b1v;
            if (RELU) {
                v00 = fmaxf(v00, 0.f); v01 = fmaxf(v01, 0.f);
                v10 = fmaxf(v10, 0.f); v11 = fmaxf(v11, 0.f);
            }
            long i0 = (long)row0 * N + col;
            long i1 = (long)(row0 + 8) * N + col;
            if (OUTF) {
                *(float2*)&Cf[i0] = make_float2(v00, v01);
                *(float2*)&Cf[i1] = make_float2(v10, v11);
            }
            if (OUTB) {
                __nv_bfloat16 h0, l0, h1, l1;
                split2(v00, &h0, &l0); split2(v01, &h1, &l1);
                *(__nv_bfloat162*)&Ch_[i0] = __nv_bfloat162(h0, h1);
                *(__nv_bfloat162*)&Cl_[i0] = __nv_bfloat162(l0, l1);
                split2(v10, &h0, &l0); split2(v11, &h1, &l1);
                *(__nv_bfloat162*)&Ch_[i1] = __nv_bfloat162(h0, h1);
                *(__nv_bfloat162*)&Cl_[i1] = __nv_bfloat162(l0, l1);
            }
        }
    }
}

// ---------------- weight prep: transpose [K,N] fp32 -> [N,K] bf16 hi/lo ----------------
__global__ void k_wsplit(const float* __restrict__ W, __nv_bfloat16* __restrict__ oh,
                         __nv_bfloat16* __restrict__ ol, int K, int N) {
    __shared__ float s[32][33];
    int bx = blockIdx.x * 32, by = blockIdx.y * 32;
    int tx = threadIdx.x, ty = threadIdx.y;   // (32, 8)
#pragma unroll
    for (int r = 0; r < 32; r += 8)
        s[ty + r][tx] = W[(long)(by + ty + r) * N + bx + tx];
    __syncthreads();
#pragma unroll
    for (int r = 0; r < 32; r += 8) {
        float v = s[tx][ty + r];
        long o = (long)(bx + ty + r) * K + by + tx;
        split2(v, &oh[o], &ol[o]);
    }
}

__global__ void k_bpack(const float* __restrict__ bq, const float* __restrict__ bk,
                        const float* __restrict__ bv, float* __restrict__ out) {
    int i = blockIdx.x * 256 + threadIdx.x;
    if (i >= L_ * 3 * D_) return;
    int l = i / (3 * D_), r = (i / D_) % 3, d = i % D_;
    const float* s = (r == 0) ? bq : (r == 1) ? bk : bv;
    out[i] = s[l * D_ + d];
}

// ---------------- elementwise ----------------
__global__ void k_embed(const int* __restrict__ x, const float* __restrict__ tok,
                        const float* __restrict__ pos, float* __restrict__ h) {
    int i = blockIdx.x * blockDim.x + threadIdx.x;
    if (i >= NBTD) return;
    int d = i % D_, bt = i / D_, t = bt % T_;
    float s = rsqrtf((float)D_);
    h[i] = tok[(long)x[bt] * D_ + d] * s + pos[t * D_ + d] * s;
}

__global__ void k_addpos(const float* __restrict__ h, const float* __restrict__ pos,
                         float* __restrict__ e, __nv_bfloat16* __restrict__ eh,
                         __nv_bfloat16* __restrict__ el) {
    int i = blockIdx.x * blockDim.x + threadIdx.x;
    if (i >= NBTD) return;
    int td = i % (T_*D_);
    float s = rsqrtf((float)D_);
    float v = h[i] + pos[td] * s;
    e[i] = v;
    split2(v, &eh[i], &el[i]);
}

__global__ void k_ew(const float* __restrict__ wb, float* __restrict__ ew) {
    int t = blockIdx.x, j = threadIdx.x;
    bool valid = (j <= t);
    float w = valid ? wb[(long)t*T_ + (t - j)] : -1e30f;
    __shared__ float sm[64];
    sm[j] = w; __syncthreads();
    for (int off = 32; off > 0; off >>= 1) {
        if (j < off) sm[j] = fmaxf(sm[j], sm[j + off]);
        __syncthreads();
    }
    ew[t*WIN + j] = valid ? expf(w - sm[0]) : 0.f;
}

__global__ void k_kmax_part(const float* __restrict__ K, float* __restrict__ part) {
    int b = blockIdx.y, z = blockIdx.x, d = threadIdx.x;
    float m = -INFINITY;
    int t0 = z * (T_/8);
#pragma unroll 4
    for (int t = t0; t < t0 + T_/8; t++)
        m = fmaxf(m, K[((long)b*T_ + t)*D_ + d]);
    part[(b*8 + z)*D_ + d] = m;
}
__global__ void k_kmax_red(const float* __restrict__ part, float* __restrict__ kmax) {
    int b = blockIdx.x, d = threadIdx.x;
    float m = -INFINITY;
#pragma unroll
    for (int z = 0; z < 8; z++) m = fmaxf(m, part[(b*8 + z)*D_ + d]);
    kmax[b*D_ + d] = m;
}

__global__ void k_ekv(float* __restrict__ K, float* __restrict__ V,
                      const float* __restrict__ kmax) {
    int i = blockIdx.x * blockDim.x + threadIdx.x;
    if (i >= NBTD) return;
    int d = i % D_, b = i / (T_*D_);
    float ek = expf(K[i] - kmax[b*D_ + d]);
    K[i] = ek;
    V[i] = ek * V[i];
}

__global__ void k_band(const float* __restrict__ Q, const float* __restrict__ EK,
                       const float* __restrict__ EKV, const float* __restrict__ ew,
                       __nv_bfloat16* __restrict__ Yh, __nv_bfloat16* __restrict__ Yl) {
    int t = blockIdx.x, b = blockIdx.y;
    int tid = threadIdx.x;
    __shared__ float sw[WIN];
    if (tid < WIN) sw[tid] = ew[t*WIN + tid];
    __syncthreads();
    int jmax = min(t, WIN - 1);
    long rowt = ((long)b*T_ + t) * D_;
#pragma unroll
    for (int r = 0; r < 2; r++) {
        int d = tid + r*256;
        float num = 0.f, den = 0.f;
        for (int j = 0; j <= jmax; j++) {
            float w = sw[j];
            long rowu = ((long)b*T_ + (t - j)) * D_;
            num = fmaf(w, EKV[rowu + d], num);
            den = fmaf(w, EK [rowu + d], den);
        }
        float q = Q[rowt + d];
        float sig = 1.f / (1.f + expf(-q));
        float y = sig * num / (den + 1e-9f);
        split2(y, &Yh[rowt + d], &Yl[rowt + d]);
    }
}

template<int OUTB>
__global__ void k_resid_ln(const float* __restrict__ X, const float* __restrict__ R,
                           const float* __restrict__ g, const float* __restrict__ bta,
                           float* __restrict__ out,
                           __nv_bfloat16* __restrict__ oh, __nv_bfloat16* __restrict__ ol) {
    int row = blockIdx.x, tid = threadIdx.x;
    long base = (long)row * D_;
    float x0 = X[base + tid]       + R[base + tid];
    float x1 = X[base + tid + 256] + R[base + tid + 256];
    __shared__ float2 red[256];
    red[tid] = make_float2(x0 + x1, x0*x0 + x1*x1);
    __syncthreads();
    for (int off = 128; off > 0; off >>= 1) {
        if (tid < off) {
            red[tid].x += red[tid+off].x;
            red[tid].y += red[tid+off].y;
        }
        __syncthreads();
    }
    float mean = red[0].x * (1.f/D_);
    float var  = red[0].y * (1.f/D_) - mean*mean;
    float rs = rsqrtf(var + 1e-5f);
    float o0 = (x0 - mean)*rs*g[tid]       + bta[tid];
    float o1 = (x1 - mean)*rs*g[tid + 256] + bta[tid + 256];
    out[base + tid]       = o0;
    out[base + tid + 256] = o1;
    if (OUTB) {
        split2(o0, &oh[base + tid],       &ol[base + tid]);
        split2(o1, &oh[base + tid + 256], &ol[base + tid + 256]);
    }
}

// ---------------- orchestration ----------------
extern "C" void kernel_launch(void* const* d_in, const int* in_sizes, int n_in,
                              void* d_out, int out_size) {
    const int*   x     = (const int*)  d_in[0];
    const float* tok   = (const float*)d_in[1];
    const float* pos   = (const float*)d_in[2];
    const float* Wq    = (const float*)d_in[3];
    const float* bq    = (const float*)d_in[4];
    const float* Wk    = (const float*)d_in[5];
    const float* bk    = (const float*)d_in[6];
    const float* Wv    = (const float*)d_in[7];
    const float* bv    = (const float*)d_in[8];
    const float* Wo    = (const float*)d_in[9];
    const float* bo    = (const float*)d_in[10];
    const float* wbias = (const float*)d_in[11];
    const float* lng   = (const float*)d_in[12];
    const float* lnb   = (const float*)d_in[13];
    const float* W1    = (const float*)d_in[14];
    const float* b1    = (const float*)d_in[15];
    const float* W2    = (const float*)d_in[16];
    const float* b2    = (const float*)d_in[17];
    float* H = (float*)d_out;

    float *E, *QKV, *A, *AOf, *EW, *KP, *KM, *BP;
    __nv_bfloat16 *Eh, *El, *Yh, *Yl, *AOh, *AOl, *F1h, *F1l, *Wth, *Wtl;
    cudaGetSymbolAddress((void**)&E,   g_E);
    cudaGetSymbolAddress((void**)&QKV, g_QKV);
    cudaGetSymbolAddress((void**)&A,   g_A);
    cudaGetSymbolAddress((void**)&AOf, g_AOf);
    cudaGetSymbolAddress((void**)&EW,  g_ew);
    cudaGetSymbolAddress((void**)&KP,  g_kpart);
    cudaGetSymbolAddress((void**)&KM,  g_kmax);
    cudaGetSymbolAddress((void**)&BP,  g_bpack);
    cudaGetSymbolAddress((void**)&Eh,  g_Eh);  cudaGetSymbolAddress((void**)&El,  g_El);
    cudaGetSymbolAddress((void**)&Yh,  g_Yh);  cudaGetSymbolAddress((void**)&Yl,  g_Yl);
    cudaGetSymbolAddress((void**)&AOh, g_AOh); cudaGetSymbolAddress((void**)&AOl, g_AOl);
    cudaGetSymbolAddress((void**)&F1h, g_F1h); cudaGetSymbolAddress((void**)&F1l, g_F1l);
    cudaGetSymbolAddress((void**)&Wth, g_Wth); cudaGetSymbolAddress((void**)&Wtl, g_Wtl);

    cudaFuncSetAttribute(tc_gemm<0,1,0>, cudaFuncAttributeMaxDynamicSharedMemorySize, DSM_BYTES);
    cudaFuncSetAttribute(tc_gemm<1,0,1>, cudaFuncAttributeMaxDynamicSharedMemorySize, DSM_BYTES);

    // ---- weight prep ----
    dim3 wblk(32, 8);
    for (int l = 0; l < L_; l++) {
        long lo = (long)l * WL;
        k_wsplit<<<dim3(D_/32, D_/32), wblk>>>(Wq + (long)l*D_*D_, Wth + lo + OFF_WQ, Wtl + lo + OFF_WQ, D_, D_);
        k_wsplit<<<dim3(D_/32, D_/32), wblk>>>(Wk + (long)l*D_*D_, Wth + lo + OFF_WK, Wtl + lo + OFF_WK, D_, D_);
        k_wsplit<<<dim3(D_/32, D_/32), wblk>>>(Wv + (long)l*D_*D_, Wth + lo + OFF_WV, Wtl + lo + OFF_WV, D_, D_);
        k_wsplit<<<dim3(D_/32, D_/32), wblk>>>(Wo + (long)l*D_*D_, Wth + lo + OFF_WO, Wtl + lo + OFF_WO, D_, D_);
        k_wsplit<<<dim3(H_/32, D_/32), wblk>>>(W1 + (long)l*D_*H_, Wth + lo + OFF_W1, Wtl + lo + OFF_W1, D_, H_);
        k_wsplit<<<dim3(D_/32, H_/32), wblk>>>(W2 + (long)l*H_*D_, Wth + lo + OFF_W2, Wtl + lo + OFF_W2, H_, D_);
    }
    k_bpack<<<(L_*3*D_ + 255)/256, 256>>>(bq, bk, bv, BP);

    const int EL_BLK = 256;
    const int EL_GRID = (NBTD + EL_BLK - 1) / EL_BLK;

    k_embed<<<EL_GRID, EL_BLK>>>(x, tok, pos, H);

    float* Qf = QKV;
    float* Kf = QKV + (long)NBTD;
    float* Vf = QKV + 2L*NBTD;

    for (int l = 0; l < L_; l++) {
        long lo = (long)l * WL;
        const float* wbi = wbias + (long)l*T_*T_;
        const float* gi  = lng + l*D_;
        const float* bi  = lnb + l*D_;

        k_addpos<<<EL_GRID, EL_BLK>>>(H, pos, E, Eh, El);

        // QKV: batched, grid.z = 3
        tc_gemm<0,1,0><<<dim3(D_/128, MT/128, 3), 256, DSM_BYTES>>>(
            Eh, El, Wth + lo, Wtl + lo, BP + (long)l*3*D_,
            QKV, nullptr, nullptr, MT, D_, D_,
            (long)D_*D_, (long)D_, (long)NBTD);

        k_ew<<<T_, WIN>>>(wbi, EW);
        k_kmax_part<<<dim3(8, B_), D_>>>(Kf, KP);
        k_kmax_red<<<B_, D_>>>(KP, KM);
        k_ekv<<<EL_GRID, EL_BLK>>>(Kf, Vf, KM);

        k_band<<<dim3(T_, B_), 256>>>(Qf, Kf, Vf, EW, Yh, Yl);

        // O projection
        tc_gemm<0,1,0><<<dim3(D_/128, MT/128, 1), 256, DSM_BYTES>>>(
            Yh, Yl, Wth + lo + OFF_WO, Wtl + lo + OFF_WO, bo + (long)l*D_,
            A, nullptr, nullptr, MT, D_, D_, 0, 0, 0);

        k_resid_ln<1><<<MT, 256>>>(A, E, gi, bi, AOf, AOh, AOl);

        // FFN1 (ReLU, bf16 split output only)
        tc_gemm<1,0,1><<<dim3(H_/128, MT/128, 1), 256, DSM_BYTES>>>(
            AOh, AOl, Wth + lo + OFF_W1, Wtl + lo + OFF_W1, b1 + (long)l*H_,
            nullptr, F1h, F1l, MT, H_, D_, 0, 0, 0);

        // FFN2 -> E (fp32)
        tc_gemm<0,1,0><<<dim3(D_/128, MT/128, 1), 256, DSM_BYTES>>>(
            F1h, F1l, Wth + lo + OFF_W2, Wtl + lo + OFF_W2, b2 + (long)l*D_,
            E, nullptr, nullptr, MT, D_, H_, 0, 0, 0);

        k_resid_ln<0><<<MT, 256>>>(E, AOf, gi, bi, H, nullptr, nullptr);
    }
}

// round 10
// speedup vs baseline: 2.1336x; 1.1045x over previous
#include <cuda_runtime.h>
#include <cuda_bf16.h>
#include <math.h>
#include <stdint.h>

#define B_   4
#define T_   1024
#define D_   512
#define H_   2048
#define L_   6
#define WIN  64
#define MT   (B_*T_)          // 4096 rows
#define NBTD (B_*T_*D_)       // 2,097,152

#define WL   (4*D_*D_ + D_*H_ + H_*D_)
#define OFF_WQ 0
#define OFF_WK (D_*D_)
#define OFF_WV (2*D_*D_)
#define OFF_WO (3*D_*D_)
#define OFF_W1 (4*D_*D_)
#define OFF_W2 (4*D_*D_ + D_*H_)

// ---------------- scratch (static __device__, alloc-free) ----------------
__device__ __align__(16) float g_E[NBTD];
__device__ __align__(16) float g_QKV[3*NBTD];
__device__ __align__(16) float g_A[NBTD];
__device__ __align__(16) float g_AOf[NBTD];
__device__ __align__(16) float2 g_P[NBTD];          // (ek, ek*v)
__device__ __align__(16) __nv_bfloat16 g_Eh[NBTD],  g_El[NBTD];
__device__ __align__(16) __nv_bfloat16 g_Yh[NBTD],  g_Yl[NBTD];
__device__ __align__(16) __nv_bfloat16 g_AOh[NBTD], g_AOl[NBTD];
__device__ __align__(16) __nv_bfloat16 g_F1h[MT*H_], g_F1l[MT*H_];
__device__ __align__(16) __nv_bfloat16 g_Wth[L_*WL], g_Wtl[L_*WL];
__device__ __align__(16) float g_bpack[L_*3*D_];
__device__ float g_ew[T_*WIN];
__device__ float g_kpart[B_*8*D_];
__device__ float g_kmax[B_*D_];

// ---------------- helpers ----------------
__device__ __forceinline__ void split2(float x, __nv_bfloat16* h, __nv_bfloat16* l) {
    __nv_bfloat16 hh = __float2bfloat16(x);
    *h = hh;
    *l = __float2bfloat16(x - __bfloat162float(hh));
}
__device__ __forceinline__ uint32_t smem_u32(const void* p) {
    uint32_t a;
    asm("{ .reg .u64 t; cvta.to.shared.u64 t, %1; cvt.u32.u64 %0, t; }" : "=r"(a) : "l"(p));
    return a;
}
__device__ __forceinline__ void cpa16(uint32_t s, const void* g) {
    asm volatile("cp.async.cg.shared.global [%0], [%1], 16;" :: "r"(s), "l"(g));
}
__device__ __forceinline__ void ldmx4(uint32_t* r, uint32_t addr) {
    asm volatile("ldmatrix.sync.aligned.m8n8.x4.shared.b16 {%0,%1,%2,%3}, [%4];"
        : "=r"(r[0]), "=r"(r[1]), "=r"(r[2]), "=r"(r[3]) : "r"(addr));
}
__device__ __forceinline__ void mma16816(float* c, const uint32_t* a, uint32_t b0, uint32_t b1) {
    asm volatile("mma.sync.aligned.m16n8k16.row.col.f32.bf16.bf16.f32 "
        "{%0,%1,%2,%3}, {%4,%5,%6,%7}, {%8,%9}, {%0,%1,%2,%3};"
        : "+f"(c[0]), "+f"(c[1]), "+f"(c[2]), "+f"(c[3])
        : "r"(a[0]), "r"(a[1]), "r"(a[2]), "r"(a[3]), "r"(b0), "r"(b1));
}

// ---------------- HMMA GEMM (unchanged from R9, passing) ----------------
#define STAGES 4
#define SSTAGE 32768
#define SA_H 0
#define SA_L 8192
#define SB_H 16384
#define SB_L 24576
#define DSM_BYTES (STAGES*SSTAGE)

template<int RELU, int OUTF, int OUTB>
__global__ void __launch_bounds__(256, 1)
tc_gemm(const __nv_bfloat16* __restrict__ Ah_, const __nv_bfloat16* __restrict__ Al_,
        const __nv_bfloat16* __restrict__ Bh_, const __nv_bfloat16* __restrict__ Bl_,
        const float* __restrict__ bias_, float* Cf_,
        __nv_bfloat16* Ch_, __nv_bfloat16* Cl_,
        int M, int N, int K, long sB, long sBias, long sC) {
    extern __shared__ __align__(1024) char dsm[];
    int t = threadIdx.x;
    int wid = t >> 5, l = t & 31;
    int wy = wid & 3, wx = wid >> 2;
    int z = blockIdx.z;
    int bn = blockIdx.x * 128, bm = blockIdx.y * 128;

    const __nv_bfloat16* Ahp = Ah_;
    const __nv_bfloat16* Alp = Al_;
    const __nv_bfloat16* Bhp = Bh_ + (long)z * sB;
    const __nv_bfloat16* Blp = Bl_ + (long)z * sB;
    const float* bias = bias_ + (long)z * sBias;
    float* Cf = Cf_ ? (Cf_ + (long)z * sC) : nullptr;

    uint32_t sbase = smem_u32(dsm);

    int ra = t >> 2, kb = t & 3;
    int rb2 = ra + 64;
    long gA0 = (long)(bm + ra)  * K + kb * 8;
    long gA1 = (long)(bm + rb2) * K + kb * 8;
    long gB0 = (long)(bn + ra)  * K + kb * 8;
    long gB1 = (long)(bn + rb2) * K + kb * 8;
    uint32_t sO0 = (uint32_t)((ra  >> 3) * 512 + kb * 128 + (ra  & 7) * 16);
    uint32_t sO1 = (uint32_t)((rb2 >> 3) * 512 + kb * 128 + (rb2 & 7) * 16);

    auto load_stage = [&](int st, int kc) {
        uint32_t sb = sbase + st * SSTAGE;
        cpa16(sb + SA_H + sO0, Ahp + gA0 + kc);
        cpa16(sb + SA_H + sO1, Ahp + gA1 + kc);
        cpa16(sb + SA_L + sO0, Alp + gA0 + kc);
        cpa16(sb + SA_L + sO1, Alp + gA1 + kc);
        cpa16(sb + SB_H + sO0, Bhp + gB0 + kc);
        cpa16(sb + SB_H + sO1, Bhp + gB1 + kc);
        cpa16(sb + SB_L + sO0, Blp + gB0 + kc);
        cpa16(sb + SB_L + sO1, Blp + gB1 + kc);
    };

    uint32_t lr = (uint32_t)((l & 7) * 16);
    uint32_t offA[2][2], offB[4][2];
#pragma unroll
    for (int mi = 0; mi < 2; mi++)
#pragma unroll
        for (int ks = 0; ks < 2; ks++) {
            int tr = wy*4 + mi*2 + ((l >> 3) & 1);
            int tk = ks*2 + ((l >> 4) & 1);
            offA[mi][ks] = (uint32_t)((tr*4 + tk) * 128) + lr;
        }
#pragma unroll
    for (int j = 0; j < 4; j++)
#pragma unroll
        for (int ks = 0; ks < 2; ks++) {
            int tn = wx*8 + 2*j + ((l >> 4) & 1);
            int tk = ks*2 + ((l >> 3) & 1);
            offB[j][ks] = (uint32_t)((tn*4 + tk) * 128) + lr;
        }

    int nk = K >> 5;
    load_stage(0, 0);   asm volatile("cp.async.commit_group;");
    load_stage(1, 32);  asm volatile("cp.async.commit_group;");
    load_stage(2, 64);  asm volatile("cp.async.commit_group;");
    asm volatile("cp.async.wait_group 2;");
    __syncthreads();

    float acc[2][8][4] = {};

    for (int kt = 0; kt < nk; kt++) {
        if (kt + 3 < nk) load_stage((kt + 3) & 3, (kt + 3) * 32);
        asm volatile("cp.async.commit_group;");

        uint32_t sb = sbase + (kt & 3) * SSTAGE;
#pragma unroll
        for (int ks = 0; ks < 2; ks++) {
            uint32_t ah[2][4], al[2][4], bh[4][4], bl[4][4];
#pragma unroll
            for (int mi = 0; mi < 2; mi++) {
                ldmx4(ah[mi], sb + SA_H + offA[mi][ks]);
                ldmx4(al[mi], sb + SA_L + offA[mi][ks]);
            }
#pragma unroll
            for (int j = 0; j < 4; j++) {
                ldmx4(bh[j], sb + SB_H + offB[j][ks]);
                ldmx4(bl[j], sb + SB_L + offB[j][ks]);
            }
#pragma unroll
            for (int mi = 0; mi < 2; mi++)
#pragma unroll
                for (int j = 0; j < 4; j++) {
                    mma16816(acc[mi][2*j],   ah[mi], bh[j][0], bh[j][1]);
                    mma16816(acc[mi][2*j+1], ah[mi], bh[j][2], bh[j][3]);
                    mma16816(acc[mi][2*j],   ah[mi], bl[j][0], bl[j][1]);
                    mma16816(acc[mi][2*j+1], ah[mi], bl[j][2], bl[j][3]);
                    mma16816(acc[mi][2*j],   al[mi], bh[j][0], bh[j][1]);
                    mma16816(acc[mi][2*j+1], al[mi], bh[j][2], bh[j][3]);
                }
        }
        asm volatile("cp.async.wait_group 2;");
        __syncthreads();
    }

    int gid = l >> 2, tg = l & 3;
#pragma unroll
    for (int mi = 0; mi < 2; mi++) {
        int row0 = bm + wy*32 + mi*16 + gid;
#pragma unroll
        for (int nt = 0; nt < 8; nt++) {
            int col = bn + wx*64 + nt*8 + tg*2;
            float b0v = bias[col], b1v = bias[col + 1];
            float v00 = acc[mi][nt][0] + b0v, v01 = acc[mi][nt][1] + b1v;
            float v10 = acc[mi][nt][2] + b0v, v11 = acc[mi][nt][3] + b1v;
            if (RELU) {
                v00 = fmaxf(v00, 0.f); v01 = fmaxf(v01, 0.f);
                v10 = fmaxf(v10, 0.f); v11 = fmaxf(v11, 0.f);
            }
            long i0 = (long)row0 * N + col;
            long i1 = (long)(row0 + 8) * N + col;
            if (OUTF) {
                *(float2*)&Cf[i0] = make_float2(v00, v01);
                *(float2*)&Cf[i1] = make_float2(v10, v11);
            }
            if (OUTB) {
                __nv_bfloat16 h0, l0, h1, l1;
                split2(v00, &h0, &l0); split2(v01, &h1, &l1);
                *(__nv_bfloat162*)&Ch_[i0] = __nv_bfloat162(h0, h1);
                *(__nv_bfloat162*)&Cl_[i0] = __nv_bfloat162(l0, l1);
                split2(v10, &h0, &l0); split2(v11, &h1, &l1);
                *(__nv_bfloat162*)&Ch_[i1] = __nv_bfloat162(h0, h1);
                *(__nv_bfloat162*)&Cl_[i1] = __nv_bfloat162(l0, l1);
            }
        }
    }
}

// ---------------- batched weight prep ----------------
// transpose 32x32 tile of [K,N] fp32 -> [N,K] bf16 hi/lo
__device__ __forceinline__ void wsplit_tile(const float* __restrict__ W,
                                            __nv_bfloat16* __restrict__ oh,
                                            __nv_bfloat16* __restrict__ ol,
                                            int K, int N) {
    __shared__ float s[32][33];
    int bx = blockIdx.x * 32, by = blockIdx.y * 32;
    int tx = threadIdx.x, ty = threadIdx.y;   // (32, 8)
#pragma unroll
    for (int r = 0; r < 32; r += 8)
        s[ty + r][tx] = W[(long)(by + ty + r) * N + bx + tx];
    __syncthreads();
#pragma unroll
    for (int r = 0; r < 32; r += 8) {
        float v = s[tx][ty + r];
        long o = (long)(bx + ty + r) * K + by + tx;
        split2(v, &oh[o], &ol[o]);
    }
}

// QKVO: grid.z = L*4
__global__ void k_wsplit_qkvo(const float* __restrict__ Wq, const float* __restrict__ Wk,
                              const float* __restrict__ Wv, const float* __restrict__ Wo,
                              __nv_bfloat16* __restrict__ oh, __nv_bfloat16* __restrict__ ol) {
    int z = blockIdx.z, l = z >> 2, w = z & 3;
    const float* W = (w == 0 ? Wq : w == 1 ? Wk : w == 2 ? Wv : Wo) + (long)l * D_ * D_;
    long off = (long)l * WL + (long)w * D_ * D_;
    wsplit_tile(W, oh + off, ol + off, D_, D_);
}

// generic per-layer: grid.z = L
__global__ void k_wsplitL(const float* __restrict__ W, __nv_bfloat16* __restrict__ oh,
                          __nv_bfloat16* __restrict__ ol, int K, int N, long woff) {
    int l = blockIdx.z;
    long off = (long)l * WL + woff;
    wsplit_tile(W + (long)l * K * N, oh + off, ol + off, K, N);
}

__global__ void k_bpack(const float* __restrict__ bq, const float* __restrict__ bk,
                        const float* __restrict__ bv, float* __restrict__ out) {
    int i = blockIdx.x * 256 + threadIdx.x;
    if (i >= L_ * 3 * D_) return;
    int l = i / (3 * D_), r = (i / D_) % 3, d = i % D_;
    const float* s = (r == 0) ? bq : (r == 1) ? bk : bv;
    out[i] = s[l * D_ + d];
}

// ---------------- elementwise ----------------
__global__ void k_embed(const int* __restrict__ x, const float* __restrict__ tok,
                        const float* __restrict__ pos, float* __restrict__ h) {
    int i = blockIdx.x * blockDim.x + threadIdx.x;
    if (i >= NBTD) return;
    int d = i % D_, bt = i / D_, t = bt % T_;
    float s = rsqrtf((float)D_);
    h[i] = tok[(long)x[bt] * D_ + d] * s + pos[t * D_ + d] * s;
}

__global__ void k_addpos(const float* __restrict__ h, const float* __restrict__ pos,
                         float* __restrict__ e, __nv_bfloat16* __restrict__ eh,
                         __nv_bfloat16* __restrict__ el) {
    int i = blockIdx.x * blockDim.x + threadIdx.x;
    if (i >= NBTD) return;
    int td = i % (T_*D_);
    float s = rsqrtf((float)D_);
    float v = h[i] + pos[td] * s;
    e[i] = v;
    split2(v, &eh[i], &el[i]);
}

__global__ void k_ew(const float* __restrict__ wb, float* __restrict__ ew) {
    int t = blockIdx.x, j = threadIdx.x;
    bool valid = (j <= t);
    float w = valid ? wb[(long)t*T_ + (t - j)] : -1e30f;
    __shared__ float sm[64];
    sm[j] = w; __syncthreads();
    for (int off = 32; off > 0; off >>= 1) {
        if (j < off) sm[j] = fmaxf(sm[j], sm[j + off]);
        __syncthreads();
    }
    ew[t*WIN + j] = valid ? expf(w - sm[0]) : 0.f;
}

__global__ void k_kmax_part(const float* __restrict__ K, float* __restrict__ part) {
    int b = blockIdx.y, z = blockIdx.x, d = threadIdx.x;
    float m = -INFINITY;
    int t0 = z * (T_/8);
#pragma unroll 4
    for (int t = t0; t < t0 + T_/8; t++)
        m = fmaxf(m, K[((long)b*T_ + t)*D_ + d]);
    part[(b*8 + z)*D_ + d] = m;
}
__global__ void k_kmax_red(const float* __restrict__ part, float* __restrict__ kmax) {
    int b = blockIdx.x, d = threadIdx.x;
    float m = -INFINITY;
#pragma unroll
    for (int z = 0; z < 8; z++) m = fmaxf(m, part[(b*8 + z)*D_ + d]);
    kmax[b*D_ + d] = m;
}

// P = (ek, ek*v)
__global__ void k_ekv2(const float* __restrict__ K, const float* __restrict__ V,
                       const float* __restrict__ kmax, float2* __restrict__ P) {
    int i = blockIdx.x * blockDim.x + threadIdx.x;
    if (i >= NBTD) return;
    int d = i % D_, b = i / (T_*D_);
    float ek = expf(K[i] - kmax[b*D_ + d]);
    P[i] = make_float2(ek, ek * V[i]);
}

// ---------------- tiled banded AFT ----------------
// block: 64 t x 32 d; each thread owns 8 consecutive t, 1 d.
// Sliding register window over the (ek,ekv) rows exploits the diagonal band.
#define TBB 64
#define DBB 32
__global__ void __launch_bounds__(256, 4)
k_band2(const float* __restrict__ Qf, const float2* __restrict__ P,
        const float* __restrict__ ew,
        __nv_bfloat16* __restrict__ Yh, __nv_bfloat16* __restrict__ Yl) {
    __shared__ float2 sp[127 * DBB];
    __shared__ float  sw[TBB * WIN];
    int t0 = blockIdx.x * TBB;
    int b  = blockIdx.y;
    int d0 = blockIdx.z * DBB;
    int tid = threadIdx.x;

    for (int i = tid; i < 127 * DBB; i += 256) {
        int r = i / DBB, dd = i % DBB;
        int u = t0 - 63 + r;
        sp[i] = (u >= 0) ? P[((long)b*T_ + u)*D_ + d0 + dd] : make_float2(0.f, 0.f);
    }
    for (int i = tid; i < TBB * WIN; i += 256)
        sw[i] = ew[(long)(t0 + i/WIN)*WIN + (i % WIN)];
    __syncthreads();

    int dd = tid & 31, tq = tid >> 5;
    int tb = tq * 8;

    float2 win[8];
#pragma unroll
    for (int i = 0; i < 8; i++) win[i] = sp[(tb + i + 63)*DBB + dd];

    float num[8] = {}, den[8] = {};
#pragma unroll 8
    for (int j = 0; j < WIN; j++) {
#pragma unroll
        for (int i = 0; i < 8; i++) {
            float w = sw[(tb + i)*WIN + j];
            num[i] = fmaf(w, win[i].y, num[i]);
            den[i] = fmaf(w, win[i].x, den[i]);
        }
        if (j < WIN - 1) {
#pragma unroll
            for (int i = 7; i >= 1; i--) win[i] = win[i-1];
            win[0] = sp[(tb + 62 - j)*DBB + dd];
        }
    }

#pragma unroll
    for (int i = 0; i < 8; i++) {
        int t = t0 + tb + i;
        long idx = ((long)b*T_ + t)*D_ + d0 + dd;
        float q = Qf[idx];
        float sig = 1.f / (1.f + expf(-q));
        float y = sig * num[i] / (den[i] + 1e-9f);
        split2(y, &Yh[idx], &Yl[idx]);
    }
}

template<int OUTB>
__global__ void k_resid_ln(const float* __restrict__ X, const float* __restrict__ R,
                           const float* __restrict__ g, const float* __restrict__ bta,
                           float* __restrict__ out,
                           __nv_bfloat16* __restrict__ oh, __nv_bfloat16* __restrict__ ol) {
    int row = blockIdx.x, tid = threadIdx.x;
    long base = (long)row * D_;
    float x0 = X[base + tid]       + R[base + tid];
    float x1 = X[base + tid + 256] + R[base + tid + 256];
    __shared__ float2 red[256];
    red[tid] = make_float2(x0 + x1, x0*x0 + x1*x1);
    __syncthreads();
    for (int off = 128; off > 0; off >>= 1) {
        if (tid < off) {
            red[tid].x += red[tid+off].x;
            red[tid].y += red[tid+off].y;
        }
        __syncthreads();
    }
    float mean = red[0].x * (1.f/D_);
    float var  = red[0].y * (1.f/D_) - mean*mean;
    float rs = rsqrtf(var + 1e-5f);
    float o0 = (x0 - mean)*rs*g[tid]       + bta[tid];
    float o1 = (x1 - mean)*rs*g[tid + 256] + bta[tid + 256];
    out[base + tid]       = o0;
    out[base + tid + 256] = o1;
    if (OUTB) {
        split2(o0, &oh[base + tid],       &ol[base + tid]);
        split2(o1, &oh[base + tid + 256], &ol[base + tid + 256]);
    }
}

// ---------------- orchestration ----------------
extern "C" void kernel_launch(void* const* d_in, const int* in_sizes, int n_in,
                              void* d_out, int out_size) {
    const int*   x     = (const int*)  d_in[0];
    const float* tok   = (const float*)d_in[1];
    const float* pos   = (const float*)d_in[2];
    const float* Wq    = (const float*)d_in[3];
    const float* bq    = (const float*)d_in[4];
    const float* Wk    = (const float*)d_in[5];
    const float* bk    = (const float*)d_in[6];
    const float* Wv    = (const float*)d_in[7];
    const float* bv    = (const float*)d_in[8];
    const float* Wo    = (const float*)d_in[9];
    const float* bo    = (const float*)d_in[10];
    const float* wbias = (const float*)d_in[11];
    const float* lng   = (const float*)d_in[12];
    const float* lnb   = (const float*)d_in[13];
    const float* W1    = (const float*)d_in[14];
    const float* b1    = (const float*)d_in[15];
    const float* W2    = (const float*)d_in[16];
    const float* b2    = (const float*)d_in[17];
    float* H = (float*)d_out;

    float *E, *QKV, *A, *AOf, *EW, *KP, *KM, *BP;
    float2* P;
    __nv_bfloat16 *Eh, *El, *Yh, *Yl, *AOh, *AOl, *F1h, *F1l, *Wth, *Wtl;
    cudaGetSymbolAddress((void**)&E,   g_E);
    cudaGetSymbolAddress((void**)&QKV, g_QKV);
    cudaGetSymbolAddress((void**)&A,   g_A);
    cudaGetSymbolAddress((void**)&AOf, g_AOf);
    cudaGetSymbolAddress((void**)&P,   g_P);
    cudaGetSymbolAddress((void**)&EW,  g_ew);
    cudaGetSymbolAddress((void**)&KP,  g_kpart);
    cudaGetSymbolAddress((void**)&KM,  g_kmax);
    cudaGetSymbolAddress((void**)&BP,  g_bpack);
    cudaGetSymbolAddress((void**)&Eh,  g_Eh);  cudaGetSymbolAddress((void**)&El,  g_El);
    cudaGetSymbolAddress((void**)&Yh,  g_Yh);  cudaGetSymbolAddress((void**)&Yl,  g_Yl);
    cudaGetSymbolAddress((void**)&AOh, g_AOh); cudaGetSymbolAddress((void**)&AOl, g_AOl);
    cudaGetSymbolAddress((void**)&F1h, g_F1h); cudaGetSymbolAddress((void**)&F1l, g_F1l);
    cudaGetSymbolAddress((void**)&Wth, g_Wth); cudaGetSymbolAddress((void**)&Wtl, g_Wtl);

    cudaFuncSetAttribute(tc_gemm<0,1,0>, cudaFuncAttributeMaxDynamicSharedMemorySize, DSM_BYTES);
    cudaFuncSetAttribute(tc_gemm<1,0,1>, cudaFuncAttributeMaxDynamicSharedMemorySize, DSM_BYTES);

    // ---- weight prep (3 batched launches) ----
    dim3 wblk(32, 8);
    k_wsplit_qkvo<<<dim3(D_/32, D_/32, L_*4), wblk>>>(Wq, Wk, Wv, Wo, Wth, Wtl);
    k_wsplitL<<<dim3(H_/32, D_/32, L_), wblk>>>(W1, Wth, Wtl, D_, H_, OFF_W1);
    k_wsplitL<<<dim3(D_/32, H_/32, L_), wblk>>>(W2, Wth, Wtl, H_, D_, OFF_W2);
    k_bpack<<<(L_*3*D_ + 255)/256, 256>>>(bq, bk, bv, BP);

    const int EL_BLK = 256;
    const int EL_GRID = (NBTD + EL_BLK - 1) / EL_BLK;

    k_embed<<<EL_GRID, EL_BLK>>>(x, tok, pos, H);

    float* Qf = QKV;
    float* Kf = QKV + (long)NBTD;
    float* Vf = QKV + 2L*NBTD;

    for (int l = 0; l < L_; l++) {
        long lo = (long)l * WL;
        const float* wbi = wbias + (long)l*T_*T_;
        const float* gi  = lng + l*D_;
        const float* bi  = lnb + l*D_;

        k_addpos<<<EL_GRID, EL_BLK>>>(H, pos, E, Eh, El);

        // QKV: batched, grid.z = 3
        tc_gemm<0,1,0><<<dim3(D_/128, MT/128, 3), 256, DSM_BYTES>>>(
            Eh, El, Wth + lo, Wtl + lo, BP + (long)l*3*D_,
            QKV, nullptr, nullptr, MT, D_, D_,
            (long)D_*D_, (long)D_, (long)NBTD);

        k_ew<<<T_, WIN>>>(wbi, EW);
        k_kmax_part<<<dim3(8, B_), D_>>>(Kf, KP);
        k_kmax_red<<<B_, D_>>>(KP, KM);
        k_ekv2<<<EL_GRID, EL_BLK>>>(Kf, Vf, KM, P);

        k_band2<<<dim3(T_/TBB, B_, D_/DBB), 256>>>(Qf, P, EW, Yh, Yl);

        // O projection
        tc_gemm<0,1,0><<<dim3(D_/128, MT/128, 1), 256, DSM_BYTES>>>(
            Yh, Yl, Wth + lo + OFF_WO, Wtl + lo + OFF_WO, bo + (long)l*D_,
            A, nullptr, nullptr, MT, D_, D_, 0, 0, 0);

        k_resid_ln<1><<<MT, 256>>>(A, E, gi, bi, AOf, AOh, AOl);

        // FFN1 (ReLU, bf16 split output only)
        tc_gemm<1,0,1><<<dim3(H_/128, MT/128, 1), 256, DSM_BYTES>>>(
            AOh, AOl, Wth + lo + OFF_W1, Wtl + lo + OFF_W1, b1 + (long)l*H_,
            nullptr, F1h, F1l, MT, H_, D_, 0, 0, 0);

        // FFN2 -> E (fp32)
        tc_gemm<0,1,0><<<dim3(D_/128, MT/128, 1), 256, DSM_BYTES>>>(
            F1h, F1l, Wth + lo + OFF_W2, Wtl + lo + OFF_W2, b2 + (long)l*D_,
            E, nullptr, nullptr, MT, D_, H_, 0, 0, 0);

        k_resid_ln<0><<<MT, 256>>>(E, AOf, gi, bi, H, nullptr, nullptr);
    }
}

// round 11
// speedup vs baseline: 2.2237x; 1.0422x over previous
#include <cuda_runtime.h>
#include <cuda_bf16.h>
#include <math.h>
#include <stdint.h>

#define B_   4
#define T_   1024
#define D_   512
#define H_   2048
#define L_   6
#define WIN  64
#define MT   (B_*T_)          // 4096 rows
#define NBTD (B_*T_*D_)       // 2,097,152

#define WL   (4*D_*D_ + D_*H_ + H_*D_)
#define OFF_WQ 0
#define OFF_WK (D_*D_)
#define OFF_WV (2*D_*D_)
#define OFF_WO (3*D_*D_)
#define OFF_W1 (4*D_*D_)
#define OFF_W2 (4*D_*D_ + D_*H_)

// ---------------- scratch (static __device__, alloc-free) ----------------
__device__ __align__(16) float g_E[NBTD];
__device__ __align__(16) float g_QKV[3*NBTD];
__device__ __align__(16) float g_A[NBTD];
__device__ __align__(16) float g_AOf[NBTD];
__device__ __align__(16) __nv_bfloat16 g_Eh[NBTD],  g_El[NBTD];
__device__ __align__(16) __nv_bfloat16 g_Yh[NBTD],  g_Yl[NBTD];
__device__ __align__(16) __nv_bfloat16 g_AOh[NBTD], g_AOl[NBTD];
__device__ __align__(16) __nv_bfloat16 g_F1h[MT*H_], g_F1l[MT*H_];
__device__ __align__(16) __nv_bfloat16 g_Wth[L_*WL], g_Wtl[L_*WL];
__device__ __align__(16) float g_bpack[L_*3*D_];
__device__ float g_ew[T_*WIN];
__device__ float g_kpart[B_*8*D_];
__device__ float g_kmax[B_*D_];

// ---------------- helpers ----------------
__device__ __forceinline__ void split2(float x, __nv_bfloat16* h, __nv_bfloat16* l) {
    __nv_bfloat16 hh = __float2bfloat16(x);
    *h = hh;
    *l = __float2bfloat16(x - __bfloat162float(hh));
}
__device__ __forceinline__ uint32_t smem_u32(const void* p) {
    uint32_t a;
    asm("{ .reg .u64 t; cvta.to.shared.u64 t, %1; cvt.u32.u64 %0, t; }" : "=r"(a) : "l"(p));
    return a;
}
__device__ __forceinline__ void cpa16(uint32_t s, const void* g) {
    asm volatile("cp.async.cg.shared.global [%0], [%1], 16;" :: "r"(s), "l"(g));
}
__device__ __forceinline__ void ldmx4(uint32_t* r, uint32_t addr) {
    asm volatile("ldmatrix.sync.aligned.m8n8.x4.shared.b16 {%0,%1,%2,%3}, [%4];"
        : "=r"(r[0]), "=r"(r[1]), "=r"(r[2]), "=r"(r[3]) : "r"(addr));
}
__device__ __forceinline__ void mma16816(float* c, const uint32_t* a, uint32_t b0, uint32_t b1) {
    asm volatile("mma.sync.aligned.m16n8k16.row.col.f32.bf16.bf16.f32 "
        "{%0,%1,%2,%3}, {%4,%5,%6,%7}, {%8,%9}, {%0,%1,%2,%3};"
        : "+f"(c[0]), "+f"(c[1]), "+f"(c[2]), "+f"(c[3])
        : "r"(a[0]), "r"(a[1]), "r"(a[2]), "r"(a[3]), "r"(b0), "r"(b1));
}

// ---------------- HMMA GEMM: 512 threads, 16 warps, warp tile 32x32 ----------------
// A: [M,K] bf16 hi/lo; B: [N,K] bf16 hi/lo (K-major). grid (N/128, M/128, NZ).
// SMEM per stage: 4 sub-tiles of 8KB (Ah,Al,Bh,Bl); atoms:
//   offset = (row/8)*512 + kchunk*128 + (row%8)*16, kchunk in [0,4).
#define STAGES 4
#define SSTAGE 32768
#define SA_H 0
#define SA_L 8192
#define SB_H 16384
#define SB_L 24576
#define DSM_BYTES (STAGES*SSTAGE)

template<int RELU, int OUTF, int OUTB>
__global__ void __launch_bounds__(512, 1)
tc_gemm(const __nv_bfloat16* __restrict__ Ah_, const __nv_bfloat16* __restrict__ Al_,
        const __nv_bfloat16* __restrict__ Bh_, const __nv_bfloat16* __restrict__ Bl_,
        const float* __restrict__ bias_, float* Cf_,
        __nv_bfloat16* Ch_, __nv_bfloat16* Cl_,
        int M, int N, int K, long sB, long sBias, long sC) {
    extern __shared__ __align__(1024) char dsm[];
    int t = threadIdx.x;
    int wid = t >> 5, l = t & 31;
    int wy = wid & 3, wx = wid >> 2;       // warp tile: rows wy*32, cols wx*32
    int z = blockIdx.z;
    int bn = blockIdx.x * 128, bm = blockIdx.y * 128;

    const __nv_bfloat16* Ahp = Ah_;
    const __nv_bfloat16* Alp = Al_;
    const __nv_bfloat16* Bhp = Bh_ + (long)z * sB;
    const __nv_bfloat16* Blp = Bl_ + (long)z * sB;
    const float* bias = bias_ + (long)z * sBias;
    float* Cf = Cf_ ? (Cf_ + (long)z * sC) : nullptr;

    uint32_t sbase = smem_u32(dsm);

    // cp.async mapping: 512 threads, 1x16B per tile per thread per stage
    int ra = t >> 2, kb = t & 3;
    long gA = (long)(bm + ra) * K + kb * 8;
    long gB = (long)(bn + ra) * K + kb * 8;
    uint32_t sO = (uint32_t)((ra >> 3) * 512 + kb * 128 + (ra & 7) * 16);

    auto load_stage = [&](int st, int kc) {
        uint32_t sb = sbase + st * SSTAGE;
        cpa16(sb + SA_H + sO, Ahp + gA + kc);
        cpa16(sb + SA_L + sO, Alp + gA + kc);
        cpa16(sb + SB_H + sO, Bhp + gB + kc);
        cpa16(sb + SB_L + sO, Blp + gB + kc);
    };

    uint32_t lr = (uint32_t)((l & 7) * 16);
    uint32_t offA[2][2], offB[2][2];
#pragma unroll
    for (int mi = 0; mi < 2; mi++)
#pragma unroll
        for (int ks = 0; ks < 2; ks++) {
            int tr = wy*4 + mi*2 + ((l >> 3) & 1);
            int tk = ks*2 + ((l >> 4) & 1);
            offA[mi][ks] = (uint32_t)((tr*4 + tk) * 128) + lr;
        }
#pragma unroll
    for (int j = 0; j < 2; j++)
#pragma unroll
        for (int ks = 0; ks < 2; ks++) {
            int tn = wx*4 + 2*j + ((l >> 4) & 1);
            int tk = ks*2 + ((l >> 3) & 1);
            offB[j][ks] = (uint32_t)((tn*4 + tk) * 128) + lr;
        }

    int nk = K >> 5;
    load_stage(0, 0);   asm volatile("cp.async.commit_group;");
    load_stage(1, 32);  asm volatile("cp.async.commit_group;");
    load_stage(2, 64);  asm volatile("cp.async.commit_group;");
    asm volatile("cp.async.wait_group 2;");
    __syncthreads();

    float acc[2][4][4] = {};

    for (int kt = 0; kt < nk; kt++) {
        if (kt + 3 < nk) load_stage((kt + 3) & 3, (kt + 3) * 32);
        asm volatile("cp.async.commit_group;");

        uint32_t sb = sbase + (kt & 3) * SSTAGE;
#pragma unroll
        for (int ks = 0; ks < 2; ks++) {
            uint32_t ah[2][4], al[2][4], bh[2][4], bl[2][4];
#pragma unroll
            for (int mi = 0; mi < 2; mi++) {
                ldmx4(ah[mi], sb + SA_H + offA[mi][ks]);
                ldmx4(al[mi], sb + SA_L + offA[mi][ks]);
            }
#pragma unroll
            for (int j = 0; j < 2; j++) {
                ldmx4(bh[j], sb + SB_H + offB[j][ks]);
                ldmx4(bl[j], sb + SB_L + offB[j][ks]);
            }
#pragma unroll
            for (int mi = 0; mi < 2; mi++)
#pragma unroll
                for (int j = 0; j < 2; j++) {
                    mma16816(acc[mi][2*j],   ah[mi], bh[j][0], bh[j][1]);
                    mma16816(acc[mi][2*j+1], ah[mi], bh[j][2], bh[j][3]);
                    mma16816(acc[mi][2*j],   ah[mi], bl[j][0], bl[j][1]);
                    mma16816(acc[mi][2*j+1], ah[mi], bl[j][2], bl[j][3]);
                    mma16816(acc[mi][2*j],   al[mi], bh[j][0], bh[j][1]);
                    mma16816(acc[mi][2*j+1], al[mi], bh[j][2], bh[j][3]);
                }
        }
        asm volatile("cp.async.wait_group 2;");
        __syncthreads();
    }

    int gid = l >> 2, tg = l & 3;
#pragma unroll
    for (int mi = 0; mi < 2; mi++) {
        int row0 = bm + wy*32 + mi*16 + gid;
#pragma unroll
        for (int nt = 0; nt < 4; nt++) {
            int col = bn + wx*32 + nt*8 + tg*2;
            float b0v = bias[col], b1v = bias[col + 1];
            float v00 = acc[mi][nt][0] + b0v, v01 = acc[mi][nt][1] + b1v;
            float v10 = acc[mi][nt][2] + b0v, v11 = acc[mi][nt][3] + b1v;
            if (RELU) {
                v00 = fmaxf(v00, 0.f); v01 = fmaxf(v01, 0.f);
                v10 = fmaxf(v10, 0.f); v11 = fmaxf(v11, 0.f);
            }
            long i0 = (long)row0 * N + col;
            long i1 = (long)(row0 + 8) * N + col;
            if (OUTF) {
                *(float2*)&Cf[i0] = make_float2(v00, v01);
                *(float2*)&Cf[i1] = make_float2(v10, v11);
            }
            if (OUTB) {
                __nv_bfloat16 h0, l0, h1, l1;
                split2(v00, &h0, &l0); split2(v01, &h1, &l1);
                *(__nv_bfloat162*)&Ch_[i0] = __nv_bfloat162(h0, h1);
                *(__nv_bfloat162*)&Cl_[i0] = __nv_bfloat162(l0, l1);
                split2(v10, &h0, &l0); split2(v11, &h1, &l1);
                *(__nv_bfloat162*)&Ch_[i1] = __nv_bfloat162(h0, h1);
                *(__nv_bfloat162*)&Cl_[i1] = __nv_bfloat162(l0, l1);
            }
        }
    }
}

// ---------------- batched weight prep ----------------
__device__ __forceinline__ void wsplit_tile(const float* __restrict__ W,
                                            __nv_bfloat16* __restrict__ oh,
                                            __nv_bfloat16* __restrict__ ol,
                                            int K, int N) {
    __shared__ float s[32][33];
    int bx = blockIdx.x * 32, by = blockIdx.y * 32;
    int tx = threadIdx.x, ty = threadIdx.y;   // (32, 8)
#pragma unroll
    for (int r = 0; r < 32; r += 8)
        s[ty + r][tx] = W[(long)(by + ty + r) * N + bx + tx];
    __syncthreads();
#pragma unroll
    for (int r = 0; r < 32; r += 8) {
        float v = s[tx][ty + r];
        long o = (long)(bx + ty + r) * K + by + tx;
        split2(v, &oh[o], &ol[o]);
    }
}

__global__ void k_wsplit_qkvo(const float* __restrict__ Wq, const float* __restrict__ Wk,
                              const float* __restrict__ Wv, const float* __restrict__ Wo,
                              __nv_bfloat16* __restrict__ oh, __nv_bfloat16* __restrict__ ol) {
    int z = blockIdx.z, l = z >> 2, w = z & 3;
    const float* W = (w == 0 ? Wq : w == 1 ? Wk : w == 2 ? Wv : Wo) + (long)l * D_ * D_;
    long off = (long)l * WL + (long)w * D_ * D_;
    wsplit_tile(W, oh + off, ol + off, D_, D_);
}

__global__ void k_wsplitL(const float* __restrict__ W, __nv_bfloat16* __restrict__ oh,
                          __nv_bfloat16* __restrict__ ol, int K, int N, long woff) {
    int l = blockIdx.z;
    long off = (long)l * WL + woff;
    wsplit_tile(W + (long)l * K * N, oh + off, ol + off, K, N);
}

__global__ void k_bpack(const float* __restrict__ bq, const float* __restrict__ bk,
                        const float* __restrict__ bv, float* __restrict__ out) {
    int i = blockIdx.x * 256 + threadIdx.x;
    if (i >= L_ * 3 * D_) return;
    int l = i / (3 * D_), r = (i / D_) % 3, d = i % D_;
    const float* s = (r == 0) ? bq : (r == 1) ? bk : bv;
    out[i] = s[l * D_ + d];
}

// ---------------- embedding, fused with E = h + pos*s + splits ----------------
__global__ void k_embed2(const int* __restrict__ x, const float* __restrict__ tok,
                         const float* __restrict__ pos, float* __restrict__ h,
                         float* __restrict__ e, __nv_bfloat16* __restrict__ eh,
                         __nv_bfloat16* __restrict__ el) {
    int i = blockIdx.x * blockDim.x + threadIdx.x;
    if (i >= NBTD) return;
    int d = i % D_, bt = i / D_, t = bt % T_;
    float s = rsqrtf((float)D_);
    float p = pos[t * D_ + d] * s;
    float hv = tok[(long)x[bt] * D_ + d] * s + p;
    h[i] = hv;
    float ev = hv + p;
    e[i] = ev;
    split2(ev, &eh[i], &el[i]);
}

__global__ void k_ew(const float* __restrict__ wb, float* __restrict__ ew) {
    int t = blockIdx.x, j = threadIdx.x;
    bool valid = (j <= t);
    float w = valid ? wb[(long)t*T_ + (t - j)] : -1e30f;
    __shared__ float sm[64];
    sm[j] = w; __syncthreads();
    for (int off = 32; off > 0; off >>= 1) {
        if (j < off) sm[j] = fmaxf(sm[j], sm[j + off]);
        __syncthreads();
    }
    ew[t*WIN + j] = valid ? expf(w - sm[0]) : 0.f;
}

__global__ void k_kmax_part(const float* __restrict__ K, float* __restrict__ part) {
    int b = blockIdx.y, z = blockIdx.x, d = threadIdx.x;
    float m = -INFINITY;
    int t0 = z * (T_/8);
#pragma unroll 4
    for (int t = t0; t < t0 + T_/8; t++)
        m = fmaxf(m, K[((long)b*T_ + t)*D_ + d]);
    part[(b*8 + z)*D_ + d] = m;
}
__global__ void k_kmax_red(const float* __restrict__ part, float* __restrict__ kmax) {
    int b = blockIdx.x, d = threadIdx.x;
    float m = -INFINITY;
#pragma unroll
    for (int z = 0; z < 8; z++) m = fmaxf(m, part[(b*8 + z)*D_ + d]);
    kmax[b*D_ + d] = m;
}

// ---------------- tiled banded AFT, ek computed inline ----------------
#define TBB 64
#define DBB 32
__global__ void __launch_bounds__(256, 3)
k_band3(const float* __restrict__ Qf, const float* __restrict__ Kf,
        const float* __restrict__ Vf, const float* __restrict__ kmax,
        const float* __restrict__ ew,
        __nv_bfloat16* __restrict__ Yh, __nv_bfloat16* __restrict__ Yl) {
    __shared__ float2 sp[127 * DBB];
    __shared__ float  sw[TBB * WIN];
    int t0 = blockIdx.x * TBB;
    int b  = blockIdx.y;
    int d0 = blockIdx.z * DBB;
    int tid = threadIdx.x;

    for (int i = tid; i < 127 * DBB; i += 256) {
        int r = i / DBB, dd = i % DBB;
        int u = t0 - 63 + r;
        if (u >= 0) {
            long idx = ((long)b*T_ + u)*D_ + d0 + dd;
            float ek = expf(Kf[idx] - kmax[b*D_ + d0 + dd]);
            sp[i] = make_float2(ek, ek * Vf[idx]);
        } else {
            sp[i] = make_float2(0.f, 0.f);
        }
    }
    for (int i = tid; i < TBB * WIN; i += 256)
        sw[i] = ew[(long)(t0 + i/WIN)*WIN + (i % WIN)];
    __syncthreads();

    int dd = tid & 31, tq = tid >> 5;
    int tb = tq * 8;

    float2 win[8];
#pragma unroll
    for (int i = 0; i < 8; i++) win[i] = sp[(tb + i + 63)*DBB + dd];

    float num[8] = {}, den[8] = {};
#pragma unroll 8
    for (int j = 0; j < WIN; j++) {
#pragma unroll
        for (int i = 0; i < 8; i++) {
            float w = sw[(tb + i)*WIN + j];
            num[i] = fmaf(w, win[i].y, num[i]);
            den[i] = fmaf(w, win[i].x, den[i]);
        }
        if (j < WIN - 1) {
#pragma unroll
            for (int i = 7; i >= 1; i--) win[i] = win[i-1];
            win[0] = sp[(tb + 62 - j)*DBB + dd];
        }
    }

#pragma unroll
    for (int i = 0; i < 8; i++) {
        int t = t0 + tb + i;
        long idx = ((long)b*T_ + t)*D_ + d0 + dd;
        float q = Qf[idx];
        float sig = 1.f / (1.f + expf(-q));
        float y = sig * num[i] / (den[i] + 1e-9f);
        split2(y, &Yh[idx], &Yl[idx]);
    }
}

// ---------------- LayerNorm(X + R), optionally fused with E = out + pos*s ----------------
// OUTB: write bf16 splits. POS: splits are of (out + pos*s) into e/oh/ol instead of out.
template<int OUTB, int POS>
__global__ void k_resid_ln(const float* __restrict__ X, const float* __restrict__ R,
                           const float* __restrict__ g, const float* __restrict__ bta,
                           float* __restrict__ out,
                           __nv_bfloat16* __restrict__ oh, __nv_bfloat16* __restrict__ ol,
                           const float* __restrict__ pos, float* __restrict__ e) {
    int row = blockIdx.x, tid = threadIdx.x;
    long base = (long)row * D_;
    float x0 = X[base + tid]       + R[base + tid];
    float x1 = X[base + tid + 256] + R[base + tid + 256];
    __shared__ float2 red[256];
    red[tid] = make_float2(x0 + x1, x0*x0 + x1*x1);
    __syncthreads();
    for (int off = 128; off > 0; off >>= 1) {
        if (tid < off) {
            red[tid].x += red[tid+off].x;
            red[tid].y += red[tid+off].y;
        }
        __syncthreads();
    }
    float mean = red[0].x * (1.f/D_);
    float var  = red[0].y * (1.f/D_) - mean*mean;
    float rs = rsqrtf(var + 1e-5f);
    float o0 = (x0 - mean)*rs*g[tid]       + bta[tid];
    float o1 = (x1 - mean)*rs*g[tid + 256] + bta[tid + 256];
    out[base + tid]       = o0;
    out[base + tid + 256] = o1;
    if (POS) {
        int t = row % T_;
        float s = rsqrtf((float)D_);
        float e0 = o0 + pos[(long)t*D_ + tid] * s;
        float e1 = o1 + pos[(long)t*D_ + tid + 256] * s;
        e[base + tid]       = e0;
        e[base + tid + 256] = e1;
        split2(e0, &oh[base + tid],       &ol[base + tid]);
        split2(e1, &oh[base + tid + 256], &ol[base + tid + 256]);
    } else if (OUTB) {
        split2(o0, &oh[base + tid],       &ol[base + tid]);
        split2(o1, &oh[base + tid + 256], &ol[base + tid + 256]);
    }
}

// ---------------- orchestration ----------------
extern "C" void kernel_launch(void* const* d_in, const int* in_sizes, int n_in,
                              void* d_out, int out_size) {
    const int*   x     = (const int*)  d_in[0];
    const float* tok   = (const float*)d_in[1];
    const float* pos   = (const float*)d_in[2];
    const float* Wq    = (const float*)d_in[3];
    const float* bq    = (const float*)d_in[4];
    const float* Wk    = (const float*)d_in[5];
    const float* bk    = (const float*)d_in[6];
    const float* Wv    = (const float*)d_in[7];
    const float* bv    = (const float*)d_in[8];
    const float* Wo    = (const float*)d_in[9];
    const float* bo    = (const float*)d_in[10];
    const float* wbias = (const float*)d_in[11];
    const float* lng   = (const float*)d_in[12];
    const float* lnb   = (const float*)d_in[13];
    const float* W1    = (const float*)d_in[14];
    const float* b1    = (const float*)d_in[15];
    const float* W2    = (const float*)d_in[16];
    const float* b2    = (const float*)d_in[17];
    float* H = (float*)d_out;

    float *E, *QKV, *A, *AOf, *EW, *KP, *KM, *BP;
    __nv_bfloat16 *Eh, *El, *Yh, *Yl, *AOh, *AOl, *F1h, *F1l, *Wth, *Wtl;
    cudaGetSymbolAddress((void**)&E,   g_E);
    cudaGetSymbolAddress((void**)&QKV, g_QKV);
    cudaGetSymbolAddress((void**)&A,   g_A);
    cudaGetSymbolAddress((void**)&AOf, g_AOf);
    cudaGetSymbolAddress((void**)&EW,  g_ew);
    cudaGetSymbolAddress((void**)&KP,  g_kpart);
    cudaGetSymbolAddress((void**)&KM,  g_kmax);
    cudaGetSymbolAddress((void**)&BP,  g_bpack);
    cudaGetSymbolAddress((void**)&Eh,  g_Eh);  cudaGetSymbolAddress((void**)&El,  g_El);
    cudaGetSymbolAddress((void**)&Yh,  g_Yh);  cudaGetSymbolAddress((void**)&Yl,  g_Yl);
    cudaGetSymbolAddress((void**)&AOh, g_AOh); cudaGetSymbolAddress((void**)&AOl, g_AOl);
    cudaGetSymbolAddress((void**)&F1h, g_F1h); cudaGetSymbolAddress((void**)&F1l, g_F1l);
    cudaGetSymbolAddress((void**)&Wth, g_Wth); cudaGetSymbolAddress((void**)&Wtl, g_Wtl);

    cudaFuncSetAttribute(tc_gemm<0,1,0>, cudaFuncAttributeMaxDynamicSharedMemorySize, DSM_BYTES);
    cudaFuncSetAttribute(tc_gemm<1,0,1>, cudaFuncAttributeMaxDynamicSharedMemorySize, DSM_BYTES);

    // ---- weight prep ----
    dim3 wblk(32, 8);
    k_wsplit_qkvo<<<dim3(D_/32, D_/32, L_*4), wblk>>>(Wq, Wk, Wv, Wo, Wth, Wtl);
    k_wsplitL<<<dim3(H_/32, D_/32, L_), wblk>>>(W1, Wth, Wtl, D_, H_, OFF_W1);
    k_wsplitL<<<dim3(D_/32, H_/32, L_), wblk>>>(W2, Wth, Wtl, H_, D_, OFF_W2);
    k_bpack<<<(L_*3*D_ + 255)/256, 256>>>(bq, bk, bv, BP);

    const int EL_BLK = 256;
    const int EL_GRID = (NBTD + EL_BLK - 1) / EL_BLK;

    k_embed2<<<EL_GRID, EL_BLK>>>(x, tok, pos, H, E, Eh, El);

    float* Qf = QKV;
    float* Kf = QKV + (long)NBTD;
    float* Vf = QKV + 2L*NBTD;

    for (int l = 0; l < L_; l++) {
        long lo = (long)l * WL;
        const float* wbi = wbias + (long)l*T_*T_;
        const float* gi  = lng + l*D_;
        const float* bi  = lnb + l*D_;

        // QKV: batched, grid.z = 3 (E/Eh/El prepared by previous layer's LN or embed)
        tc_gemm<0,1,0><<<dim3(D_/128, MT/128, 3), 512, DSM_BYTES>>>(
            Eh, El, Wth + lo, Wtl + lo, BP + (long)l*3*D_,
            QKV, nullptr, nullptr, MT, D_, D_,
            (long)D_*D_, (long)D_, (long)NBTD);

        k_ew<<<T_, WIN>>>(wbi, EW);
        k_kmax_part<<<dim3(8, B_), D_>>>(Kf, KP);
        k_kmax_red<<<B_, D_>>>(KP, KM);

        k_band3<<<dim3(T_/TBB, B_, D_/DBB), 256>>>(Qf, Kf, Vf, KM, EW, Yh, Yl);

        // O projection
        tc_gemm<0,1,0><<<dim3(D_/128, MT/128, 1), 512, DSM_BYTES>>>(
            Yh, Yl, Wth + lo + OFF_WO, Wtl + lo + OFF_WO, bo + (long)l*D_,
            A, nullptr, nullptr, MT, D_, D_, 0, 0, 0);

        // attn_out = LN(A + E) + bf16 splits of attn_out
        k_resid_ln<1,0><<<MT, 256>>>(A, E, gi, bi, AOf, AOh, AOl, nullptr, nullptr);

        // FFN1 (ReLU, bf16 split output only)
        tc_gemm<1,0,1><<<dim3(H_/128, MT/128, 1), 512, DSM_BYTES>>>(
            AOh, AOl, Wth + lo + OFF_W1, Wtl + lo + OFF_W1, b1 + (long)l*H_,
            nullptr, F1h, F1l, MT, H_, D_, 0, 0, 0);

        // FFN2 -> A (fp32 scratch)
        tc_gemm<0,1,0><<<dim3(D_/128, MT/128, 1), 512, DSM_BYTES>>>(
            F1h, F1l, Wth + lo + OFF_W2, Wtl + lo + OFF_W2, b2 + (long)l*D_,
            A, nullptr, nullptr, MT, D_, H_, 0, 0, 0);

        // h = LN(F2 + attn_out); for l < L-1 also emit E = h + pos*s (+ splits)
        if (l < L_ - 1) {
            k_resid_ln<1,1><<<MT, 256>>>(A, AOf, gi, bi, H, Eh, El, pos, E);
        } else {
            k_resid_ln<0,0><<<MT, 256>>>(A, AOf, gi, bi, H, nullptr, nullptr, nullptr, nullptr);
        }
    }
}

// round 12
// speedup vs baseline: 2.2729x; 1.0221x over previous
#include <cuda_runtime.h>
#include <cuda_bf16.h>
#include <math.h>
#include <stdint.h>

#define B_   4
#define T_   1024
#define D_   512
#define H_   2048
#define L_   6
#define WIN  64
#define MT   (B_*T_)          // 4096 rows
#define NBTD (B_*T_*D_)       // 2,097,152

#define WL   (4*D_*D_ + D_*H_ + H_*D_)
#define OFF_WQ 0
#define OFF_WK (D_*D_)
#define OFF_WV (2*D_*D_)
#define OFF_WO (3*D_*D_)
#define OFF_W1 (4*D_*D_)
#define OFF_W2 (4*D_*D_ + D_*H_)

// ---------------- scratch (static __device__, alloc-free) ----------------
__device__ __align__(16) float g_E[NBTD];
__device__ __align__(16) float g_QKV[3*NBTD];
__device__ __align__(16) float g_A[NBTD];
__device__ __align__(16) float g_AOf[NBTD];
__device__ __align__(16) __nv_bfloat16 g_Eh[NBTD],  g_El[NBTD];
__device__ __align__(16) __nv_bfloat16 g_Yh[NBTD],  g_Yl[NBTD];
__device__ __align__(16) __nv_bfloat16 g_AOh[NBTD], g_AOl[NBTD];
__device__ __align__(16) __nv_bfloat16 g_F1h[MT*H_], g_F1l[MT*H_];
__device__ __align__(16) __nv_bfloat16 g_Wth[L_*WL], g_Wtl[L_*WL];
__device__ __align__(16) float g_bpack[L_*3*D_];
__device__ float g_ew[L_*T_*WIN];
__device__ float g_kpart[B_*32*D_];
__device__ float g_kmax[B_*D_];

// ---------------- helpers ----------------
__device__ __forceinline__ void split2(float x, __nv_bfloat16* h, __nv_bfloat16* l) {
    __nv_bfloat16 hh = __float2bfloat16(x);
    *h = hh;
    *l = __float2bfloat16(x - __bfloat162float(hh));
}
__device__ __forceinline__ uint32_t smem_u32(const void* p) {
    uint32_t a;
    asm("{ .reg .u64 t; cvta.to.shared.u64 t, %1; cvt.u32.u64 %0, t; }" : "=r"(a) : "l"(p));
    return a;
}
__device__ __forceinline__ void cpa16(uint32_t s, const void* g) {
    asm volatile("cp.async.cg.shared.global [%0], [%1], 16;" :: "r"(s), "l"(g));
}
__device__ __forceinline__ void ldmx4(uint32_t* r, uint32_t addr) {
    asm volatile("ldmatrix.sync.aligned.m8n8.x4.shared.b16 {%0,%1,%2,%3}, [%4];"
        : "=r"(r[0]), "=r"(r[1]), "=r"(r[2]), "=r"(r[3]) : "r"(addr));
}
__device__ __forceinline__ void mma16816(float* c, const uint32_t* a, uint32_t b0, uint32_t b1) {
    asm volatile("mma.sync.aligned.m16n8k16.row.col.f32.bf16.bf16.f32 "
        "{%0,%1,%2,%3}, {%4,%5,%6,%7}, {%8,%9}, {%0,%1,%2,%3};"
        : "+f"(c[0]), "+f"(c[1]), "+f"(c[2]), "+f"(c[3])
        : "r"(a[0]), "r"(a[1]), "r"(a[2]), "r"(a[3]), "r"(b0), "r"(b1));
}

// ---------------- HMMA GEMM: 512 threads, 16 warps, warp tile 32x32 ----------------
#define STAGES 4
#define SSTAGE 32768
#define SA_H 0
#define SA_L 8192
#define SB_H 16384
#define SB_L 24576
#define DSM_BYTES (STAGES*SSTAGE)

template<int RELU, int OUTF, int OUTB>
__global__ void __launch_bounds__(512, 1)
tc_gemm(const __nv_bfloat16* __restrict__ Ah_, const __nv_bfloat16* __restrict__ Al_,
        const __nv_bfloat16* __restrict__ Bh_, const __nv_bfloat16* __restrict__ Bl_,
        const float* __restrict__ bias_, float* Cf_,
        __nv_bfloat16* Ch_, __nv_bfloat16* Cl_,
        int M, int N, int K, long sB, long sBias, long sC) {
    extern __shared__ __align__(1024) char dsm[];
    int t = threadIdx.x;
    int wid = t >> 5, l = t & 31;
    int wy = wid & 3, wx = wid >> 2;
    int z = blockIdx.z;
    int bn = blockIdx.x * 128, bm = blockIdx.y * 128;

    const __nv_bfloat16* Ahp = Ah_;
    const __nv_bfloat16* Alp = Al_;
    const __nv_bfloat16* Bhp = Bh_ + (long)z * sB;
    const __nv_bfloat16* Blp = Bl_ + (long)z * sB;
    const float* bias = bias_ + (long)z * sBias;
    float* Cf = Cf_ ? (Cf_ + (long)z * sC) : nullptr;

    uint32_t sbase = smem_u32(dsm);

    int ra = t >> 2, kb = t & 3;
    long gA = (long)(bm + ra) * K + kb * 8;
    long gB = (long)(bn + ra) * K + kb * 8;
    uint32_t sO = (uint32_t)((ra >> 3) * 512 + kb * 128 + (ra & 7) * 16);

    auto load_stage = [&](int st, int kc) {
        uint32_t sb = sbase + st * SSTAGE;
        cpa16(sb + SA_H + sO, Ahp + gA + kc);
        cpa16(sb + SA_L + sO, Alp + gA + kc);
        cpa16(sb + SB_H + sO, Bhp + gB + kc);
        cpa16(sb + SB_L + sO, Blp + gB + kc);
    };

    uint32_t lr = (uint32_t)((l & 7) * 16);
    uint32_t offA[2][2], offB[2][2];
#pragma unroll
    for (int mi = 0; mi < 2; mi++)
#pragma unroll
        for (int ks = 0; ks < 2; ks++) {
            int tr = wy*4 + mi*2 + ((l >> 3) & 1);
            int tk = ks*2 + ((l >> 4) & 1);
            offA[mi][ks] = (uint32_t)((tr*4 + tk) * 128) + lr;
        }
#pragma unroll
    for (int j = 0; j < 2; j++)
#pragma unroll
        for (int ks = 0; ks < 2; ks++) {
            int tn = wx*4 + 2*j + ((l >> 4) & 1);
            int tk = ks*2 + ((l >> 3) & 1);
            offB[j][ks] = (uint32_t)((tn*4 + tk) * 128) + lr;
        }

    int nk = K >> 5;
    load_stage(0, 0);   asm volatile("cp.async.commit_group;");
    load_stage(1, 32);  asm volatile("cp.async.commit_group;");
    load_stage(2, 64);  asm volatile("cp.async.commit_group;");
    asm volatile("cp.async.wait_group 2;");
    __syncthreads();

    float acc[2][4][4] = {};

    for (int kt = 0; kt < nk; kt++) {
        if (kt + 3 < nk) load_stage((kt + 3) & 3, (kt + 3) * 32);
        asm volatile("cp.async.commit_group;");

        uint32_t sb = sbase + (kt & 3) * SSTAGE;
#pragma unroll
        for (int ks = 0; ks < 2; ks++) {
            uint32_t ah[2][4], al[2][4], bh[2][4], bl[2][4];
#pragma unroll
            for (int mi = 0; mi < 2; mi++) {
                ldmx4(ah[mi], sb + SA_H + offA[mi][ks]);
                ldmx4(al[mi], sb + SA_L + offA[mi][ks]);
            }
#pragma unroll
            for (int j = 0; j < 2; j++) {
                ldmx4(bh[j], sb + SB_H + offB[j][ks]);
                ldmx4(bl[j], sb + SB_L + offB[j][ks]);
            }
#pragma unroll
            for (int mi = 0; mi < 2; mi++)
#pragma unroll
                for (int j = 0; j < 2; j++) {
                    mma16816(acc[mi][2*j],   ah[mi], bh[j][0], bh[j][1]);
                    mma16816(acc[mi][2*j+1], ah[mi], bh[j][2], bh[j][3]);
                    mma16816(acc[mi][2*j],   ah[mi], bl[j][0], bl[j][1]);
                    mma16816(acc[mi][2*j+1], ah[mi], bl[j][2], bl[j][3]);
                    mma16816(acc[mi][2*j],   al[mi], bh[j][0], bh[j][1]);
                    mma16816(acc[mi][2*j+1], al[mi], bh[j][2], bh[j][3]);
                }
        }
        asm volatile("cp.async.wait_group 2;");
        __syncthreads();
    }

    int gid = l >> 2, tg = l & 3;
#pragma unroll
    for (int mi = 0; mi < 2; mi++) {
        int row0 = bm + wy*32 + mi*16 + gid;
#pragma unroll
        for (int nt = 0; nt < 4; nt++) {
            int col = bn + wx*32 + nt*8 + tg*2;
            float b0v = bias[col], b1v = bias[col + 1];
            float v00 = acc[mi][nt][0] + b0v, v01 = acc[mi][nt][1] + b1v;
            float v10 = acc[mi][nt][2] + b0v, v11 = acc[mi][nt][3] + b1v;
            if (RELU) {
                v00 = fmaxf(v00, 0.f); v01 = fmaxf(v01, 0.f);
                v10 = fmaxf(v10, 0.f); v11 = fmaxf(v11, 0.f);
            }
            long i0 = (long)row0 * N + col;
            long i1 = (long)(row0 + 8) * N + col;
            if (OUTF) {
                *(float2*)&Cf[i0] = make_float2(v00, v01);
                *(float2*)&Cf[i1] = make_float2(v10, v11);
            }
            if (OUTB) {
                __nv_bfloat16 h0, l0, h1, l1;
                split2(v00, &h0, &l0); split2(v01, &h1, &l1);
                *(__nv_bfloat162*)&Ch_[i0] = __nv_bfloat162(h0, h1);
                *(__nv_bfloat162*)&Cl_[i0] = __nv_bfloat162(l0, l1);
                split2(v10, &h0, &l0); split2(v11, &h1, &l1);
                *(__nv_bfloat162*)&Ch_[i1] = __nv_bfloat162(h0, h1);
                *(__nv_bfloat162*)&Cl_[i1] = __nv_bfloat162(l0, l1);
            }
        }
    }
}

// ---------------- single merged weight prep ----------------
// grid (64, 16, L_*6); z -> (layer, w) with w: 0..3 QKVO, 4 W1, 5 W2.
__device__ __forceinline__ void wsplit_tile_xy(const float* __restrict__ W,
                                               __nv_bfloat16* __restrict__ oh,
                                               __nv_bfloat16* __restrict__ ol,
                                               int K, int N, int tx32, int ty32) {
    __shared__ float s[32][33];
    int bx = tx32 * 32, by = ty32 * 32;
    int tx = threadIdx.x, ty = threadIdx.y;   // (32, 8)
#pragma unroll
    for (int r = 0; r < 32; r += 8)
        s[ty + r][tx] = W[(long)(by + ty + r) * N + bx + tx];
    __syncthreads();
#pragma unroll
    for (int r = 0; r < 32; r += 8) {
        float v = s[tx][ty + r];
        long o = (long)(bx + ty + r) * K + by + tx;
        split2(v, &oh[o], &ol[o]);
    }
}

__global__ void k_wsplit_all(const float* __restrict__ Wq, const float* __restrict__ Wk,
                             const float* __restrict__ Wv, const float* __restrict__ Wo,
                             const float* __restrict__ W1, const float* __restrict__ W2,
                             __nv_bfloat16* __restrict__ oh, __nv_bfloat16* __restrict__ ol) {
    int z = blockIdx.z, l = z / 6, w = z % 6;
    long lo = (long)l * WL;
    if (w < 4) {
        if (blockIdx.x >= 16) return;   // 512/32 tiles
        const float* W = (w == 0 ? Wq : w == 1 ? Wk : w == 2 ? Wv : Wo) + (long)l * D_ * D_;
        wsplit_tile_xy(W, oh + lo + (long)w * D_ * D_, ol + lo + (long)w * D_ * D_,
                       D_, D_, blockIdx.x, blockIdx.y);
    } else if (w == 4) {
        // W1 [D,H] -> [H,D]: x over H/32=64, y over D/32=16
        wsplit_tile_xy(W1 + (long)l * D_ * H_, oh + lo + OFF_W1, ol + lo + OFF_W1,
                       D_, H_, blockIdx.x, blockIdx.y);
    } else {
        // W2 [H,D] -> [D,H]: x over D/32=16 (use blockIdx.y), y over H/32=64 (use blockIdx.x)
        wsplit_tile_xy(W2 + (long)l * H_ * D_, oh + lo + OFF_W2, ol + lo + OFF_W2,
                       H_, D_, blockIdx.y, blockIdx.x);
    }
}

__global__ void k_bpack(const float* __restrict__ bq, const float* __restrict__ bk,
                        const float* __restrict__ bv, float* __restrict__ out) {
    int i = blockIdx.x * 256 + threadIdx.x;
    if (i >= L_ * 3 * D_) return;
    int l = i / (3 * D_), r = (i / D_) % 3, d = i % D_;
    const float* s = (r == 0) ? bq : (r == 1) ? bk : bv;
    out[i] = s[l * D_ + d];
}

// ---------------- embedding, fused with E = h + pos*s + splits ----------------
__global__ void k_embed2(const int* __restrict__ x, const float* __restrict__ tok,
                         const float* __restrict__ pos, float* __restrict__ h,
                         float* __restrict__ e, __nv_bfloat16* __restrict__ eh,
                         __nv_bfloat16* __restrict__ el) {
    int i = blockIdx.x * blockDim.x + threadIdx.x;
    if (i >= NBTD) return;
    int d = i % D_, bt = i / D_, t = bt % T_;
    float s = rsqrtf((float)D_);
    float p = pos[t * D_ + d] * s;
    float hv = tok[(long)x[bt] * D_ + d] * s + p;
    h[i] = hv;
    float ev = hv + p;
    e[i] = ev;
    split2(ev, &eh[i], &el[i]);
}

// all layers at once: grid (T_, L_), 64 threads
__global__ void k_ew_all(const float* __restrict__ wb, float* __restrict__ ew) {
    int t = blockIdx.x, li = blockIdx.y, j = threadIdx.x;
    bool valid = (j <= t);
    float w = valid ? wb[(long)li*T_*T_ + (long)t*T_ + (t - j)] : -1e30f;
    __shared__ float sm[64];
    sm[j] = w; __syncthreads();
    for (int off = 32; off > 0; off >>= 1) {
        if (j < off) sm[j] = fmaxf(sm[j], sm[j + off]);
        __syncthreads();
    }
    ew[(long)li*T_*WIN + t*WIN + j] = valid ? expf(w - sm[0]) : 0.f;
}

__global__ void k_kmax_part(const float* __restrict__ K, float* __restrict__ part) {
    int b = blockIdx.y, z = blockIdx.x, d = threadIdx.x;  // z in [0,32)
    float m = -INFINITY;
    int t0 = z * (T_/32);
#pragma unroll 4
    for (int t = t0; t < t0 + T_/32; t++)
        m = fmaxf(m, K[((long)b*T_ + t)*D_ + d]);
    part[(b*32 + z)*D_ + d] = m;
}
__global__ void k_kmax_red(const float* __restrict__ part, float* __restrict__ kmax) {
    int b = blockIdx.x, d = threadIdx.x;
    float m = -INFINITY;
#pragma unroll
    for (int z = 0; z < 32; z++) m = fmaxf(m, part[(b*32 + z)*D_ + d]);
    kmax[b*D_ + d] = m;
}

// ---------------- tiled banded AFT, ek computed inline ----------------
#define TBB 64
#define DBB 32
__global__ void __launch_bounds__(256, 3)
k_band3(const float* __restrict__ Qf, const float* __restrict__ Kf,
        const float* __restrict__ Vf, const float* __restrict__ kmax,
        const float* __restrict__ ew,
        __nv_bfloat16* __restrict__ Yh, __nv_bfloat16* __restrict__ Yl) {
    __shared__ float2 sp[127 * DBB];
    __shared__ float  sw[TBB * WIN];
    int t0 = blockIdx.x * TBB;
    int b  = blockIdx.y;
    int d0 = blockIdx.z * DBB;
    int tid = threadIdx.x;

    for (int i = tid; i < 127 * DBB; i += 256) {
        int r = i / DBB, dd = i % DBB;
        int u = t0 - 63 + r;
        if (u >= 0) {
            long idx = ((long)b*T_ + u)*D_ + d0 + dd;
            float ek = expf(Kf[idx] - kmax[b*D_ + d0 + dd]);
            sp[i] = make_float2(ek, ek * Vf[idx]);
        } else {
            sp[i] = make_float2(0.f, 0.f);
        }
    }
    for (int i = tid; i < TBB * WIN; i += 256)
        sw[i] = ew[(long)(t0 + i/WIN)*WIN + (i % WIN)];
    __syncthreads();

    int dd = tid & 31, tq = tid >> 5;
    int tb = tq * 8;

    float2 win[8];
#pragma unroll
    for (int i = 0; i < 8; i++) win[i] = sp[(tb + i + 63)*DBB + dd];

    float num[8] = {}, den[8] = {};
#pragma unroll 8
    for (int j = 0; j < WIN; j++) {
#pragma unroll
        for (int i = 0; i < 8; i++) {
            float w = sw[(tb + i)*WIN + j];
            num[i] = fmaf(w, win[i].y, num[i]);
            den[i] = fmaf(w, win[i].x, den[i]);
        }
        if (j < WIN - 1) {
#pragma unroll
            for (int i = 7; i >= 1; i--) win[i] = win[i-1];
            win[0] = sp[(tb + 62 - j)*DBB + dd];
        }
    }

#pragma unroll
    for (int i = 0; i < 8; i++) {
        int t = t0 + tb + i;
        long idx = ((long)b*T_ + t)*D_ + d0 + dd;
        float q = Qf[idx];
        float sig = 1.f / (1.f + expf(-q));
        float y = sig * num[i] / (den[i] + 1e-9f);
        split2(y, &Yh[idx], &Yl[idx]);
    }
}

// ---------------- LayerNorm(X + R), optional pos-fusion ----------------
template<int OUTB, int POS>
__global__ void k_resid_ln(const float* __restrict__ X, const float* __restrict__ R,
                           const float* __restrict__ g, const float* __restrict__ bta,
                           float* __restrict__ out,
                           __nv_bfloat16* __restrict__ oh, __nv_bfloat16* __restrict__ ol,
                           const float* __restrict__ pos, float* __restrict__ e) {
    int row = blockIdx.x, tid = threadIdx.x;
    long base = (long)row * D_;
    float x0 = X[base + tid]       + R[base + tid];
    float x1 = X[base + tid + 256] + R[base + tid + 256];
    __shared__ float2 red[256];
    red[tid] = make_float2(x0 + x1, x0*x0 + x1*x1);
    __syncthreads();
    for (int off = 128; off > 0; off >>= 1) {
        if (tid < off) {
            red[tid].x += red[tid+off].x;
            red[tid].y += red[tid+off].y;
        }
        __syncthreads();
    }
    float mean = red[0].x * (1.f/D_);
    float var  = red[0].y * (1.f/D_) - mean*mean;
    float rs = rsqrtf(var + 1e-5f);
    float o0 = (x0 - mean)*rs*g[tid]       + bta[tid];
    float o1 = (x1 - mean)*rs*g[tid + 256] + bta[tid + 256];
    out[base + tid]       = o0;
    out[base + tid + 256] = o1;
    if (POS) {
        int t = row % T_;
        float s = rsqrtf((float)D_);
        float e0 = o0 + pos[(long)t*D_ + tid] * s;
        float e1 = o1 + pos[(long)t*D_ + tid + 256] * s;
        e[base + tid]       = e0;
        e[base + tid + 256] = e1;
        split2(e0, &oh[base + tid],       &ol[base + tid]);
        split2(e1, &oh[base + tid + 256], &ol[base + tid + 256]);
    } else if (OUTB) {
        split2(o0, &oh[base + tid],       &ol[base + tid]);
        split2(o1, &oh[base + tid + 256], &ol[base + tid + 256]);
    }
}

// ---------------- orchestration ----------------
extern "C" void kernel_launch(void* const* d_in, const int* in_sizes, int n_in,
                              void* d_out, int out_size) {
    const int*   x     = (const int*)  d_in[0];
    const float* tok   = (const float*)d_in[1];
    const float* pos   = (const float*)d_in[2];
    const float* Wq    = (const float*)d_in[3];
    const float* bq    = (const float*)d_in[4];
    const float* Wk    = (const float*)d_in[5];
    const float* bk    = (const float*)d_in[6];
    const float* Wv    = (const float*)d_in[7];
    const float* bv    = (const float*)d_in[8];
    const float* Wo    = (const float*)d_in[9];
    const float* bo    = (const float*)d_in[10];
    const float* wbias = (const float*)d_in[11];
    const float* lng   = (const float*)d_in[12];
    const float* lnb   = (const float*)d_in[13];
    const float* W1    = (const float*)d_in[14];
    const float* b1    = (const float*)d_in[15];
    const float* W2    = (const float*)d_in[16];
    const float* b2    = (const float*)d_in[17];
    float* H = (float*)d_out;

    float *E, *QKV, *A, *AOf, *EW, *KP, *KM, *BP;
    __nv_bfloat16 *Eh, *El, *Yh, *Yl, *AOh, *AOl, *F1h, *F1l, *Wth, *Wtl;
    cudaGetSymbolAddress((void**)&E,   g_E);
    cudaGetSymbolAddress((void**)&QKV, g_QKV);
    cudaGetSymbolAddress((void**)&A,   g_A);
    cudaGetSymbolAddress((void**)&AOf, g_AOf);
    cudaGetSymbolAddress((void**)&EW,  g_ew);
    cudaGetSymbolAddress((void**)&KP,  g_kpart);
    cudaGetSymbolAddress((void**)&KM,  g_kmax);
    cudaGetSymbolAddress((void**)&BP,  g_bpack);
    cudaGetSymbolAddress((void**)&Eh,  g_Eh);  cudaGetSymbolAddress((void**)&El,  g_El);
    cudaGetSymbolAddress((void**)&Yh,  g_Yh);  cudaGetSymbolAddress((void**)&Yl,  g_Yl);
    cudaGetSymbolAddress((void**)&AOh, g_AOh); cudaGetSymbolAddress((void**)&AOl, g_AOl);
    cudaGetSymbolAddress((void**)&F1h, g_F1h); cudaGetSymbolAddress((void**)&F1l, g_F1l);
    cudaGetSymbolAddress((void**)&Wth, g_Wth); cudaGetSymbolAddress((void**)&Wtl, g_Wtl);

    cudaFuncSetAttribute(tc_gemm<0,1,0>, cudaFuncAttributeMaxDynamicSharedMemorySize, DSM_BYTES);
    cudaFuncSetAttribute(tc_gemm<1,0,1>, cudaFuncAttributeMaxDynamicSharedMemorySize, DSM_BYTES);

    const int EL_BLK = 256;
    const int EL_GRID = (NBTD + EL_BLK - 1) / EL_BLK;
    dim3 wblk(32, 8);

    float* Qf = QKV;
    float* Kf = QKV + (long)NBTD;
    float* Vf = QKV + 2L*NBTD;

    // launch 1..3: prep; launch 4 = layer-0 QKV GEMM (ncu window target)
    k_wsplit_all<<<dim3(64, 16, L_*6), wblk>>>(Wq, Wk, Wv, Wo, W1, W2, Wth, Wtl);
    k_bpack<<<(L_*3*D_ + 255)/256, 256>>>(bq, bk, bv, BP);
    k_embed2<<<EL_GRID, EL_BLK>>>(x, tok, pos, H, E, Eh, El);

    bool ew_done = false;

    for (int l = 0; l < L_; l++) {
        long lo = (long)l * WL;
        const float* gi  = lng + l*D_;
        const float* bi  = lnb + l*D_;

        // QKV: batched, grid.z = 3
        tc_gemm<0,1,0><<<dim3(D_/128, MT/128, 3), 512, DSM_BYTES>>>(
            Eh, El, Wth + lo, Wtl + lo, BP + (long)l*3*D_,
            QKV, nullptr, nullptr, MT, D_, D_,
            (long)D_*D_, (long)D_, (long)NBTD);

        if (!ew_done) {   // hoisted: all layers' banded weights in one launch
            k_ew_all<<<dim3(T_, L_), WIN>>>(wbias, EW);
            ew_done = true;
        }

        k_kmax_part<<<dim3(32, B_), D_>>>(Kf, KP);
        k_kmax_red<<<B_, D_>>>(KP, KM);

        k_band3<<<dim3(T_/TBB, B_, D_/DBB), 256>>>(Qf, Kf, Vf, KM, EW + (long)l*T_*WIN, Yh, Yl);

        // O projection
        tc_gemm<0,1,0><<<dim3(D_/128, MT/128, 1), 512, DSM_BYTES>>>(
            Yh, Yl, Wth + lo + OFF_WO, Wtl + lo + OFF_WO, bo + (long)l*D_,
            A, nullptr, nullptr, MT, D_, D_, 0, 0, 0);

        // attn_out = LN(A + E) + bf16 splits
        k_resid_ln<1,0><<<MT, 256>>>(A, E, gi, bi, AOf, AOh, AOl, nullptr, nullptr);

        // FFN1 (ReLU, bf16 split output only)
        tc_gemm<1,0,1><<<dim3(H_/128, MT/128, 1), 512, DSM_BYTES>>>(
            AOh, AOl, Wth + lo + OFF_W1, Wtl + lo + OFF_W1, b1 + (long)l*H_,
            nullptr, F1h, F1l, MT, H_, D_, 0, 0, 0);

        // FFN2 -> A (fp32 scratch)
        tc_gemm<0,1,0><<<dim3(D_/128, MT/128, 1), 512, DSM_BYTES>>>(
            F1h, F1l, Wth + lo + OFF_W2, Wtl + lo + OFF_W2, b2 + (long)l*D_,
            A, nullptr, nullptr, MT, D_, H_, 0, 0, 0);

        // h = LN(F2 + attn_out); for l < L-1 also emit E = h + pos*s (+ splits)
        if (l < L_ - 1) {
            k_resid_ln<1,1><<<MT, 256>>>(A, AOf, gi, bi, H, Eh, El, pos, E);
        } else {
            k_resid_ln<0,0><<<MT, 256>>>(A, AOf, gi, bi, H, nullptr, nullptr, nullptr, nullptr);
        }
    }
}

// round 13
// speedup vs baseline: 2.3392x; 1.0292x over previous
#include <cuda_runtime.h>
#include <cuda_bf16.h>
#include <math.h>
#include <stdint.h>

#define B_   4
#define T_   1024
#define D_   512
#define H_   2048
#define L_   6
#define WIN  64
#define MT   (B_*T_)          // 4096 rows
#define NBTD (B_*T_*D_)       // 2,097,152

#define WL   (4*D_*D_ + D_*H_ + H_*D_)
#define OFF_WQ 0
#define OFF_WK (D_*D_)
#define OFF_WV (2*D_*D_)
#define OFF_WO (3*D_*D_)
#define OFF_W1 (4*D_*D_)
#define OFF_W2 (4*D_*D_ + D_*H_)

// ---------------- scratch (static __device__, alloc-free) ----------------
__device__ __align__(16) float g_E[NBTD];
__device__ __align__(16) float g_QKV[3*NBTD];
__device__ __align__(16) float g_A[NBTD];
__device__ __align__(16) float g_AOf[NBTD];
__device__ __align__(16) __nv_bfloat16 g_Eh[NBTD],  g_El[NBTD];
__device__ __align__(16) __nv_bfloat16 g_Yh[NBTD],  g_Yl[NBTD];
__device__ __align__(16) __nv_bfloat16 g_AOh[NBTD], g_AOl[NBTD];
__device__ __align__(16) __nv_bfloat16 g_F1h[MT*H_], g_F1l[MT*H_];
__device__ __align__(16) __nv_bfloat16 g_Wth[L_*WL], g_Wtl[L_*WL];
__device__ __align__(16) float g_bpack[L_*3*D_];
__device__ float g_ew[L_*T_*WIN];
__device__ float g_kpart[B_*32*D_];
__device__ float g_kmax[B_*D_];

// ---------------- helpers ----------------
__device__ __forceinline__ void split2(float x, __nv_bfloat16* h, __nv_bfloat16* l) {
    __nv_bfloat16 hh = __float2bfloat16(x);
    *h = hh;
    *l = __float2bfloat16(x - __bfloat162float(hh));
}
__device__ __forceinline__ uint32_t smem_u32(const void* p) {
    uint32_t a;
    asm("{ .reg .u64 t; cvta.to.shared.u64 t, %1; cvt.u32.u64 %0, t; }" : "=r"(a) : "l"(p));
    return a;
}
__device__ __forceinline__ void cpa16(uint32_t s, const void* g) {
    asm volatile("cp.async.cg.shared.global [%0], [%1], 16;" :: "r"(s), "l"(g));
}
__device__ __forceinline__ void ldmx4(uint32_t* r, uint32_t addr) {
    asm volatile("ldmatrix.sync.aligned.m8n8.x4.shared.b16 {%0,%1,%2,%3}, [%4];"
        : "=r"(r[0]), "=r"(r[1]), "=r"(r[2]), "=r"(r[3]) : "r"(addr));
}
__device__ __forceinline__ void mma16816(float* c, const uint32_t* a, uint32_t b0, uint32_t b1) {
    asm volatile("mma.sync.aligned.m16n8k16.row.col.f32.bf16.bf16.f32 "
        "{%0,%1,%2,%3}, {%4,%5,%6,%7}, {%8,%9}, {%0,%1,%2,%3};"
        : "+f"(c[0]), "+f"(c[1]), "+f"(c[2]), "+f"(c[3])
        : "r"(a[0]), "r"(a[1]), "r"(a[2]), "r"(a[3]), "r"(b0), "r"(b1));
}

// ---------------- HMMA GEMM: 256 threads, 8 warps, warp tile 32x64 ----------------
// 3-stage pipeline, 96KB smem -> 2 CTAs/SM co-resident.
#define STAGES 3
#define SSTAGE 32768
#define SA_H 0
#define SA_L 8192
#define SB_H 16384
#define SB_L 24576
#define DSM_BYTES (STAGES*SSTAGE)

template<int RELU, int OUTF, int OUTB>
__global__ void __launch_bounds__(256, 2)
tc_gemm(const __nv_bfloat16* __restrict__ Ah_, const __nv_bfloat16* __restrict__ Al_,
        const __nv_bfloat16* __restrict__ Bh_, const __nv_bfloat16* __restrict__ Bl_,
        const float* __restrict__ bias_, float* Cf_,
        __nv_bfloat16* Ch_, __nv_bfloat16* Cl_,
        int M, int N, int K, long sB, long sBias, long sC) {
    extern __shared__ __align__(1024) char dsm[];
    int t = threadIdx.x;
    int wid = t >> 5, l = t & 31;
    int wy = wid & 3, wx = wid >> 2;       // warp tile: rows wy*32, cols wx*64
    int z = blockIdx.z;
    int bn = blockIdx.x * 128, bm = blockIdx.y * 128;

    const __nv_bfloat16* Ahp = Ah_;
    const __nv_bfloat16* Alp = Al_;
    const __nv_bfloat16* Bhp = Bh_ + (long)z * sB;
    const __nv_bfloat16* Blp = Bl_ + (long)z * sB;
    const float* bias = bias_ + (long)z * sBias;
    float* Cf = Cf_ ? (Cf_ + (long)z * sC) : nullptr;

    uint32_t sbase = smem_u32(dsm);

    // cp.async mapping: 256 threads, 2x16B per sub-tile per thread per stage
    int ra = t >> 2, kb = t & 3;
    int rb2 = ra + 64;
    long gA0 = (long)(bm + ra)  * K + kb * 8;
    long gA1 = (long)(bm + rb2) * K + kb * 8;
    long gB0 = (long)(bn + ra)  * K + kb * 8;
    long gB1 = (long)(bn + rb2) * K + kb * 8;
    uint32_t sO0 = (uint32_t)((ra  >> 3) * 512 + kb * 128 + (ra  & 7) * 16);
    uint32_t sO1 = (uint32_t)((rb2 >> 3) * 512 + kb * 128 + (rb2 & 7) * 16);

    auto load_stage = [&](int st, int kc) {
        uint32_t sb = sbase + st * SSTAGE;
        cpa16(sb + SA_H + sO0, Ahp + gA0 + kc);
        cpa16(sb + SA_H + sO1, Ahp + gA1 + kc);
        cpa16(sb + SA_L + sO0, Alp + gA0 + kc);
        cpa16(sb + SA_L + sO1, Alp + gA1 + kc);
        cpa16(sb + SB_H + sO0, Bhp + gB0 + kc);
        cpa16(sb + SB_H + sO1, Bhp + gB1 + kc);
        cpa16(sb + SB_L + sO0, Blp + gB0 + kc);
        cpa16(sb + SB_L + sO1, Blp + gB1 + kc);
    };

    uint32_t lr = (uint32_t)((l & 7) * 16);
    uint32_t offA[2][2], offB[4][2];
#pragma unroll
    for (int mi = 0; mi < 2; mi++)
#pragma unroll
        for (int ks = 0; ks < 2; ks++) {
            int tr = wy*4 + mi*2 + ((l >> 3) & 1);
            int tk = ks*2 + ((l >> 4) & 1);
            offA[mi][ks] = (uint32_t)((tr*4 + tk) * 128) + lr;
        }
#pragma unroll
    for (int j = 0; j < 4; j++)
#pragma unroll
        for (int ks = 0; ks < 2; ks++) {
            int tn = wx*8 + 2*j + ((l >> 4) & 1);
            int tk = ks*2 + ((l >> 3) & 1);
            offB[j][ks] = (uint32_t)((tn*4 + tk) * 128) + lr;
        }

    int nk = K >> 5;
    load_stage(0, 0);   asm volatile("cp.async.commit_group;");
    load_stage(1, 32);  asm volatile("cp.async.commit_group;");
    asm volatile("cp.async.wait_group 1;");
    __syncthreads();

    float acc[2][8][4] = {};

    int st_c = 0;        // stage being computed (kt % 3)
    int st_l = 2;        // stage to load next ((kt+2) % 3)
    for (int kt = 0; kt < nk; kt++) {
        if (kt + 2 < nk) load_stage(st_l, (kt + 2) * 32);
        asm volatile("cp.async.commit_group;");

        uint32_t sb = sbase + st_c * SSTAGE;
#pragma unroll
        for (int ks = 0; ks < 2; ks++) {
            uint32_t ah[2][4], al[2][4], bh[4][4], bl[4][4];
#pragma unroll
            for (int mi = 0; mi < 2; mi++) {
                ldmx4(ah[mi], sb + SA_H + offA[mi][ks]);
                ldmx4(al[mi], sb + SA_L + offA[mi][ks]);
            }
#pragma unroll
            for (int j = 0; j < 4; j++) {
                ldmx4(bh[j], sb + SB_H + offB[j][ks]);
                ldmx4(bl[j], sb + SB_L + offB[j][ks]);
            }
#pragma unroll
            for (int mi = 0; mi < 2; mi++)
#pragma unroll
                for (int j = 0; j < 4; j++) {
                    mma16816(acc[mi][2*j],   ah[mi], bh[j][0], bh[j][1]);
                    mma16816(acc[mi][2*j+1], ah[mi], bh[j][2], bh[j][3]);
                    mma16816(acc[mi][2*j],   ah[mi], bl[j][0], bl[j][1]);
                    mma16816(acc[mi][2*j+1], ah[mi], bl[j][2], bl[j][3]);
                    mma16816(acc[mi][2*j],   al[mi], bh[j][0], bh[j][1]);
                    mma16816(acc[mi][2*j+1], al[mi], bh[j][2], bh[j][3]);
                }
        }
        asm volatile("cp.async.wait_group 1;");
        __syncthreads();
        st_c = (st_c == 2) ? 0 : st_c + 1;
        st_l = (st_l == 2) ? 0 : st_l + 1;
    }

    int gid = l >> 2, tg = l & 3;
#pragma unroll
    for (int mi = 0; mi < 2; mi++) {
        int row0 = bm + wy*32 + mi*16 + gid;
#pragma unroll
        for (int nt = 0; nt < 8; nt++) {
            int col = bn + wx*64 + nt*8 + tg*2;
            float b0v = bias[col], b1v = bias[col + 1];
            float v00 = acc[mi][nt][0] + b0v, v01 = acc[mi][nt][1] + b1v;
            float v10 = acc[mi][nt][2] + b0v, v11 = acc[mi][nt][3] + b1v;
            if (RELU) {
                v00 = fmaxf(v00, 0.f); v01 = fmaxf(v01, 0.f);
                v10 = fmaxf(v10, 0.f); v11 = fmaxf(v11, 0.f);
            }
            long i0 = (long)row0 * N + col;
            long i1 = (long)(row0 + 8) * N + col;
            if (OUTF) {
                *(float2*)&Cf[i0] = make_float2(v00, v01);
                *(float2*)&Cf[i1] = make_float2(v10, v11);
            }
            if (OUTB) {
                __nv_bfloat16 h0, l0, h1, l1;
                split2(v00, &h0, &l0); split2(v01, &h1, &l1);
                *(__nv_bfloat162*)&Ch_[i0] = __nv_bfloat162(h0, h1);
                *(__nv_bfloat162*)&Cl_[i0] = __nv_bfloat162(l0, l1);
                split2(v10, &h0, &l0); split2(v11, &h1, &l1);
                *(__nv_bfloat162*)&Ch_[i1] = __nv_bfloat162(h0, h1);
                *(__nv_bfloat162*)&Cl_[i1] = __nv_bfloat162(l0, l1);
            }
        }
    }
}

// ---------------- single merged weight prep ----------------
__device__ __forceinline__ void wsplit_tile_xy(const float* __restrict__ W,
                                               __nv_bfloat16* __restrict__ oh,
                                               __nv_bfloat16* __restrict__ ol,
                                               int K, int N, int tx32, int ty32) {
    __shared__ float s[32][33];
    int bx = tx32 * 32, by = ty32 * 32;
    int tx = threadIdx.x, ty = threadIdx.y;   // (32, 8)
#pragma unroll
    for (int r = 0; r < 32; r += 8)
        s[ty + r][tx] = W[(long)(by + ty + r) * N + bx + tx];
    __syncthreads();
#pragma unroll
    for (int r = 0; r < 32; r += 8) {
        float v = s[tx][ty + r];
        long o = (long)(bx + ty + r) * K + by + tx;
        split2(v, &oh[o], &ol[o]);
    }
}

__global__ void k_wsplit_all(const float* __restrict__ Wq, const float* __restrict__ Wk,
                             const float* __restrict__ Wv, const float* __restrict__ Wo,
                             const float* __restrict__ W1, const float* __restrict__ W2,
                             __nv_bfloat16* __restrict__ oh, __nv_bfloat16* __restrict__ ol) {
    int z = blockIdx.z, l = z / 6, w = z % 6;
    long lo = (long)l * WL;
    if (w < 4) {
        if (blockIdx.x >= 16) return;
        const float* W = (w == 0 ? Wq : w == 1 ? Wk : w == 2 ? Wv : Wo) + (long)l * D_ * D_;
        wsplit_tile_xy(W, oh + lo + (long)w * D_ * D_, ol + lo + (long)w * D_ * D_,
                       D_, D_, blockIdx.x, blockIdx.y);
    } else if (w == 4) {
        wsplit_tile_xy(W1 + (long)l * D_ * H_, oh + lo + OFF_W1, ol + lo + OFF_W1,
                       D_, H_, blockIdx.x, blockIdx.y);
    } else {
        wsplit_tile_xy(W2 + (long)l * H_ * D_, oh + lo + OFF_W2, ol + lo + OFF_W2,
                       H_, D_, blockIdx.y, blockIdx.x);
    }
}

__global__ void k_bpack(const float* __restrict__ bq, const float* __restrict__ bk,
                        const float* __restrict__ bv, float* __restrict__ out) {
    int i = blockIdx.x * 256 + threadIdx.x;
    if (i >= L_ * 3 * D_) return;
    int l = i / (3 * D_), r = (i / D_) % 3, d = i % D_;
    const float* s = (r == 0) ? bq : (r == 1) ? bk : bv;
    out[i] = s[l * D_ + d];
}

// ---------------- embedding, fused with E = h + pos*s + splits ----------------
__global__ void k_embed2(const int* __restrict__ x, const float* __restrict__ tok,
                         const float* __restrict__ pos, float* __restrict__ h,
                         float* __restrict__ e, __nv_bfloat16* __restrict__ eh,
                         __nv_bfloat16* __restrict__ el) {
    int i = blockIdx.x * blockDim.x + threadIdx.x;
    if (i >= NBTD) return;
    int d = i % D_, bt = i / D_, t = bt % T_;
    float s = rsqrtf((float)D_);
    float p = pos[t * D_ + d] * s;
    float hv = tok[(long)x[bt] * D_ + d] * s + p;
    h[i] = hv;
    float ev = hv + p;
    e[i] = ev;
    split2(ev, &eh[i], &el[i]);
}

__global__ void k_ew_all(const float* __restrict__ wb, float* __restrict__ ew) {
    int t = blockIdx.x, li = blockIdx.y, j = threadIdx.x;
    bool valid = (j <= t);
    float w = valid ? wb[(long)li*T_*T_ + (long)t*T_ + (t - j)] : -1e30f;
    __shared__ float sm[64];
    sm[j] = w; __syncthreads();
    for (int off = 32; off > 0; off >>= 1) {
        if (j < off) sm[j] = fmaxf(sm[j], sm[j + off]);
        __syncthreads();
    }
    ew[(long)li*T_*WIN + t*WIN + j] = valid ? expf(w - sm[0]) : 0.f;
}

__global__ void k_kmax_part(const float* __restrict__ K, float* __restrict__ part) {
    int b = blockIdx.y, z = blockIdx.x, d = threadIdx.x;
    float m = -INFINITY;
    int t0 = z * (T_/32);
#pragma unroll 4
    for (int t = t0; t < t0 + T_/32; t++)
        m = fmaxf(m, K[((long)b*T_ + t)*D_ + d]);
    part[(b*32 + z)*D_ + d] = m;
}
__global__ void k_kmax_red(const float* __restrict__ part, float* __restrict__ kmax) {
    int b = blockIdx.x, d = threadIdx.x;
    float m = -INFINITY;
#pragma unroll
    for (int z = 0; z < 32; z++) m = fmaxf(m, part[(b*32 + z)*D_ + d]);
    kmax[b*D_ + d] = m;
}

// ---------------- tiled banded AFT ----------------
#define TBB 64
#define DBB 32
__global__ void __launch_bounds__(256, 3)
k_band3(const float* __restrict__ Qf, const float* __restrict__ Kf,
        const float* __restrict__ Vf, const float* __restrict__ kmax,
        const float* __restrict__ ew,
        __nv_bfloat16* __restrict__ Yh, __nv_bfloat16* __restrict__ Yl) {
    __shared__ float2 sp[127 * DBB];
    __shared__ float  sw[TBB * WIN];
    int t0 = blockIdx.x * TBB;
    int b  = blockIdx.y;
    int d0 = blockIdx.z * DBB;
    int tid = threadIdx.x;

    for (int i = tid; i < 127 * DBB; i += 256) {
        int r = i / DBB, dd = i % DBB;
        int u = t0 - 63 + r;
        if (u >= 0) {
            long idx = ((long)b*T_ + u)*D_ + d0 + dd;
            float ek = expf(Kf[idx] - kmax[b*D_ + d0 + dd]);
            sp[i] = make_float2(ek, ek * Vf[idx]);
        } else {
            sp[i] = make_float2(0.f, 0.f);
        }
    }
    for (int i = tid; i < TBB * WIN; i += 256)
        sw[i] = ew[(long)(t0 + i/WIN)*WIN + (i % WIN)];
    __syncthreads();

    int dd = tid & 31, tq = tid >> 5;
    int tb = tq * 8;

    float2 win[8];
#pragma unroll
    for (int i = 0; i < 8; i++) win[i] = sp[(tb + i + 63)*DBB + dd];

    float num[8] = {}, den[8] = {};
#pragma unroll 8
    for (int j = 0; j < WIN; j++) {
#pragma unroll
        for (int i = 0; i < 8; i++) {
            float w = sw[(tb + i)*WIN + j];
            num[i] = fmaf(w, win[i].y, num[i]);
            den[i] = fmaf(w, win[i].x, den[i]);
        }
        if (j < WIN - 1) {
#pragma unroll
            for (int i = 7; i >= 1; i--) win[i] = win[i-1];
            win[0] = sp[(tb + 62 - j)*DBB + dd];
        }
    }

#pragma unroll
    for (int i = 0; i < 8; i++) {
        int t = t0 + tb + i;
        long idx = ((long)b*T_ + t)*D_ + d0 + dd;
        float q = Qf[idx];
        float sig = 1.f / (1.f + expf(-q));
        float y = sig * num[i] / (den[i] + 1e-9f);
        split2(y, &Yh[idx], &Yl[idx]);
    }
}

// ---------------- LayerNorm(X + R), optional pos-fusion ----------------
template<int OUTB, int POS>
__global__ void k_resid_ln(const float* __restrict__ X, const float* __restrict__ R,
                           const float* __restrict__ g, const float* __restrict__ bta,
                           float* __restrict__ out,
                           __nv_bfloat16* __restrict__ oh, __nv_bfloat16* __restrict__ ol,
                           const float* __restrict__ pos, float* __restrict__ e) {
    int row = blockIdx.x, tid = threadIdx.x;
    long base = (long)row * D_;
    float x0 = X[base + tid]       + R[base + tid];
    float x1 = X[base + tid + 256] + R[base + tid + 256];
    __shared__ float2 red[256];
    red[tid] = make_float2(x0 + x1, x0*x0 + x1*x1);
    __syncthreads();
    for (int off = 128; off > 0; off >>= 1) {
        if (tid < off) {
            red[tid].x += red[tid+off].x;
            red[tid].y += red[tid+off].y;
        }
        __syncthreads();
    }
    float mean = red[0].x * (1.f/D_);
    float var  = red[0].y * (1.f/D_) - mean*mean;
    float rs = rsqrtf(var + 1e-5f);
    float o0 = (x0 - mean)*rs*g[tid]       + bta[tid];
    float o1 = (x1 - mean)*rs*g[tid + 256] + bta[tid + 256];
    out[base + tid]       = o0;
    out[base + tid + 256] = o1;
    if (POS) {
        int t = row % T_;
        float s = rsqrtf((float)D_);
        float e0 = o0 + pos[(long)t*D_ + tid] * s;
        float e1 = o1 + pos[(long)t*D_ + tid + 256] * s;
        e[base + tid]       = e0;
        e[base + tid + 256] = e1;
        split2(e0, &oh[base + tid],       &ol[base + tid]);
        split2(e1, &oh[base + tid + 256], &ol[base + tid + 256]);
    } else if (OUTB) {
        split2(o0, &oh[base + tid],       &ol[base + tid]);
        split2(o1, &oh[base + tid + 256], &ol[base + tid + 256]);
    }
}

// ---------------- orchestration ----------------
extern "C" void kernel_launch(void* const* d_in, const int* in_sizes, int n_in,
                              void* d_out, int out_size) {
    const int*   x     = (const int*)  d_in[0];
    const float* tok   = (const float*)d_in[1];
    const float* pos   = (const float*)d_in[2];
    const float* Wq    = (const float*)d_in[3];
    const float* bq    = (const float*)d_in[4];
    const float* Wk    = (const float*)d_in[5];
    const float* bk    = (const float*)d_in[6];
    const float* Wv    = (const float*)d_in[7];
    const float* bv    = (const float*)d_in[8];
    const float* Wo    = (const float*)d_in[9];
    const float* bo    = (const float*)d_in[10];
    const float* wbias = (const float*)d_in[11];
    const float* lng   = (const float*)d_in[12];
    const float* lnb   = (const float*)d_in[13];
    const float* W1    = (const float*)d_in[14];
    const float* b1    = (const float*)d_in[15];
    const float* W2    = (const float*)d_in[16];
    const float* b2    = (const float*)d_in[17];
    float* H = (float*)d_out;

    float *E, *QKV, *A, *AOf, *EW, *KP, *KM, *BP;
    __nv_bfloat16 *Eh, *El, *Yh, *Yl, *AOh, *AOl, *F1h, *F1l, *Wth, *Wtl;
    cudaGetSymbolAddress((void**)&E,   g_E);
    cudaGetSymbolAddress((void**)&QKV, g_QKV);
    cudaGetSymbolAddress((void**)&A,   g_A);
    cudaGetSymbolAddress((void**)&AOf, g_AOf);
    cudaGetSymbolAddress((void**)&EW,  g_ew);
    cudaGetSymbolAddress((void**)&KP,  g_kpart);
    cudaGetSymbolAddress((void**)&KM,  g_kmax);
    cudaGetSymbolAddress((void**)&BP,  g_bpack);
    cudaGetSymbolAddress((void**)&Eh,  g_Eh);  cudaGetSymbolAddress((void**)&El,  g_El);
    cudaGetSymbolAddress((void**)&Yh,  g_Yh);  cudaGetSymbolAddress((void**)&Yl,  g_Yl);
    cudaGetSymbolAddress((void**)&AOh, g_AOh); cudaGetSymbolAddress((void**)&AOl, g_AOl);
    cudaGetSymbolAddress((void**)&F1h, g_F1h); cudaGetSymbolAddress((void**)&F1l, g_F1l);
    cudaGetSymbolAddress((void**)&Wth, g_Wth); cudaGetSymbolAddress((void**)&Wtl, g_Wtl);

    cudaFuncSetAttribute(tc_gemm<0,1,0>, cudaFuncAttributeMaxDynamicSharedMemorySize, DSM_BYTES);
    cudaFuncSetAttribute(tc_gemm<1,0,1>, cudaFuncAttributeMaxDynamicSharedMemorySize, DSM_BYTES);

    const int EL_BLK = 256;
    const int EL_GRID = (NBTD + EL_BLK - 1) / EL_BLK;
    dim3 wblk(32, 8);

    float* Qf = QKV;
    float* Kf = QKV + (long)NBTD;
    float* Vf = QKV + 2L*NBTD;

    // launch 1..3: prep; launch 4 = layer-0 QKV GEMM (ncu window target)
    k_wsplit_all<<<dim3(64, 16, L_*6), wblk>>>(Wq, Wk, Wv, Wo, W1, W2, Wth, Wtl);
    k_bpack<<<(L_*3*D_ + 255)/256, 256>>>(bq, bk, bv, BP);
    k_embed2<<<EL_GRID, EL_BLK>>>(x, tok, pos, H, E, Eh, El);

    bool ew_done = false;

    for (int l = 0; l < L_; l++) {
        long lo = (long)l * WL;
        const float* gi  = lng + l*D_;
        const float* bi  = lnb + l*D_;

        // QKV: batched, grid.z = 3
        tc_gemm<0,1,0><<<dim3(D_/128, MT/128, 3), 256, DSM_BYTES>>>(
            Eh, El, Wth + lo, Wtl + lo, BP + (long)l*3*D_,
            QKV, nullptr, nullptr, MT, D_, D_,
            (long)D_*D_, (long)D_, (long)NBTD);

        if (!ew_done) {
            k_ew_all<<<dim3(T_, L_), WIN>>>(wbias, EW);
            ew_done = true;
        }

        k_kmax_part<<<dim3(32, B_), D_>>>(Kf, KP);
        k_kmax_red<<<B_, D_>>>(KP, KM);

        k_band3<<<dim3(T_/TBB, B_, D_/DBB), 256>>>(Qf, Kf, Vf, KM, EW + (long)l*T_*WIN, Yh, Yl);

        // O projection
        tc_gemm<0,1,0><<<dim3(D_/128, MT/128, 1), 256, DSM_BYTES>>>(
            Yh, Yl, Wth + lo + OFF_WO, Wtl + lo + OFF_WO, bo + (long)l*D_,
            A, nullptr, nullptr, MT, D_, D_, 0, 0, 0);

        // attn_out = LN(A + E) + bf16 splits
        k_resid_ln<1,0><<<MT, 256>>>(A, E, gi, bi, AOf, AOh, AOl, nullptr, nullptr);

        // FFN1 (ReLU, bf16 split output only)
        tc_gemm<1,0,1><<<dim3(H_/128, MT/128, 1), 256, DSM_BYTES>>>(
            AOh, AOl, Wth + lo + OFF_W1, Wtl + lo + OFF_W1, b1 + (long)l*H_,
            nullptr, F1h, F1l, MT, H_, D_, 0, 0, 0);

        // FFN2 -> A (fp32 scratch)
        tc_gemm<0,1,0><<<dim3(D_/128, MT/128, 1), 256, DSM_BYTES>>>(
            F1h, F1l, Wth + lo + OFF_W2, Wtl + lo + OFF_W2, b2 + (long)l*D_,
            A, nullptr, nullptr, MT, D_, H_, 0, 0, 0);

        // h = LN(F2 + attn_out); for l < L-1 also emit E = h + pos*s (+ splits)
        if (l < L_ - 1) {
            k_resid_ln<1,1><<<MT, 256>>>(A, AOf, gi, bi, H, Eh, El, pos, E);
        } else {
            k_resid_ln<0,0><<<MT, 256>>>(A, AOf, gi, bi, H, nullptr, nullptr, nullptr, nullptr);
        }
    }
}